// round 5
// baseline (speedup 1.0000x reference)
#include <cuda_runtime.h>
#include <cuda_bf16.h>
#include <math.h>
#include <stdint.h>

#define Bn   4096
#define Hd   512
#define Fd   256
#define Zd   64
#define Td   16
#define Gd   2048
#define XK   832      // bf16 X row: [z(64) | y(256) | h(512)]
#define IK   1024     // infA row:   [c(512) | y_j(256) | y_prev(256)]

// ---------------- persistent buffers ----------------
__device__ float g_baseg [(size_t)Bn * Gd];    // permuted layout
__device__ float g_gates0[(size_t)Bn * Gd];    // partial, double-buffered
__device__ float g_gates1[(size_t)Bn * Gd];
__device__ float g_basehz[Bn * 128];           // [base4 | base7]
__device__ float g_hzc   [Bn * 128];           // [hz | hzp]
__device__ float g_c     [Bn * Hd];
__device__ float g_blstmp[Gd];
__device__ float g_bhz   [128];

// double-buffered state X (read buf t&1, write buf (t+1)&1)
__device__ __nv_bfloat16 g_Xh0[(size_t)Bn * XK], g_Xl0[(size_t)Bn * XK];
__device__ __nv_bfloat16 g_Xh1[(size_t)Bn * XK], g_Xl1[(size_t)Bn * XK];
__device__ __nv_bfloat16 g_Ih [(size_t)Bn * IK], g_Il [(size_t)Bn * IK];
__device__ __nv_bfloat16 g_t1h[Bn * Fd], g_t1l[Bn * Fd];
__device__ __nv_bfloat16 g_t2h[Bn * Fd], g_t2l[Bn * Fd];
__device__ __nv_bfloat16 g_hih[(size_t)Bn * Hd], g_hil[(size_t)Bn * Hd];

// weights: n-major [N][K] bf16 hi/lo
__device__ __nv_bfloat16 g_WcatT_h[(size_t)Gd * XK], g_WcatT_l[(size_t)Gd * XK];
__device__ __nv_bfloat16 g_WxhT_h [(size_t)Gd * Hd], g_WxhT_l [(size_t)Gd * Hd];
__device__ __nv_bfloat16 g_W1T_h  [Fd * Hd], g_W1T_l  [Fd * Hd];
__device__ __nv_bfloat16 g_W2T_h  [Fd * Fd], g_W2T_l  [Fd * Fd];
__device__ __nv_bfloat16 g_W3T_h  [Fd * Fd], g_W3T_l  [Fd * Fd];
__device__ __nv_bfloat16 g_WheadT_h[128 * IK], g_WheadT_l[128 * IK];
__device__ __nv_bfloat16 g_WbaseT_h[128 * Hd], g_WbaseT_l[128 * Hd];

// ---------------- helpers ----------------
__device__ __forceinline__ void bsplit(float v, __nv_bfloat16& h, __nv_bfloat16& l) {
    h = __float2bfloat16_rn(v);
    l = __float2bfloat16_rn(v - __bfloat162float(h));
}
__device__ __forceinline__ __nv_bfloat162 bmk2(__nv_bfloat16 a, __nv_bfloat16 b) {
    __nv_bfloat162 t; t.x = a; t.y = b; return t;
}
__device__ __forceinline__ void mma16816(float* c, const uint32_t* a, const uint32_t* b) {
    asm volatile(
        "mma.sync.aligned.m16n8k16.row.col.f32.bf16.bf16.f32 "
        "{%0,%1,%2,%3}, {%4,%5,%6,%7}, {%8,%9}, {%0,%1,%2,%3};\n"
        : "+f"(c[0]), "+f"(c[1]), "+f"(c[2]), "+f"(c[3])
        : "r"(a[0]), "r"(a[1]), "r"(a[2]), "r"(a[3]), "r"(b[0]), "r"(b[1]));
}
__device__ __forceinline__ void cpa16(void* dst, const void* src) {
    uint32_t d = (uint32_t)__cvta_generic_to_shared(dst);
    asm volatile("cp.async.cg.shared.global [%0], [%1], 16;\n" :: "r"(d), "l"(src));
}

struct GArgs {
    const __nv_bfloat16 *Ah, *Al; int lda;
    const __nv_bfloat16 *Bh, *Bl; int ldb;  // [N][ldb], K columns used
    const float* Ci; int ldci;
    float* C; int ldc;
    int K;
    float* cst;
    __nv_bfloat16 *Xh, *Xl;                 // WRITE state buffer (next step)
    const __nv_bfloat16 *XhR, *XlR;         // READ state buffer (current step)
    __nv_bfloat16 *Ih, *Il;
    __nv_bfloat16 *Dh, *Dl; int ldd;
    float* fake; int t;
};

template<int BM,int BN,int NTH>
__device__ __forceinline__ void stage_load(char* base, int tid, int bm, int bn,
    const __nv_bfloat16* Ah, const __nv_bfloat16* Al, int lda,
    const __nv_bfloat16* Bh, const __nv_bfloat16* Bl, int ldb, int k0)
{
#pragma unroll
    for (int i = tid; i < BM * 4; i += NTH) {
        int row = i >> 2, c4 = (i & 3) * 16;
        size_t off = ((size_t)(bm + row) * lda + k0) * 2 + c4;
        cpa16(base + row * 80 + c4, (const char*)Ah + off);
        cpa16(base + BM * 80 + row * 80 + c4, (const char*)Al + off);
    }
#pragma unroll
    for (int i = tid; i < BN * 4; i += NTH) {
        int row = i >> 2, c4 = (i & 3) * 16;
        size_t off = ((size_t)(bn + row) * ldb + k0) * 2 + c4;
        cpa16(base + BM * 160 + row * 80 + c4, (const char*)Bh + off);
        cpa16(base + BM * 160 + BN * 80 + row * 80 + c4, (const char*)Bl + off);
    }
    asm volatile("cp.async.commit_group;\n");
}

template<int BM,int BN,int MT,int NTL>
__device__ __forceinline__ void stage_mma(const char* base, float* acc,
                                          int wm, int wn, int gq, int tg)
{
    const uint32_t* As_h = (const uint32_t*)base;
    const uint32_t* As_l = (const uint32_t*)(base + BM * 80);
    const uint32_t* Bs_h = (const uint32_t*)(base + BM * 160);
    const uint32_t* Bs_l = (const uint32_t*)(base + BM * 160 + BN * 80);
#pragma unroll
    for (int kk = 0; kk < 16; kk += 8) {
        uint32_t ah[MT][4], al[MT][4], bh[NTL][2], bl[NTL][2];
#pragma unroll
        for (int mt = 0; mt < MT; mt++) {
            int r = wm + mt * 16 + gq;
            ah[mt][0] = As_h[r * 20 + kk + tg];
            ah[mt][1] = As_h[(r + 8) * 20 + kk + tg];
            ah[mt][2] = As_h[r * 20 + kk + tg + 4];
            ah[mt][3] = As_h[(r + 8) * 20 + kk + tg + 4];
            al[mt][0] = As_l[r * 20 + kk + tg];
            al[mt][1] = As_l[(r + 8) * 20 + kk + tg];
            al[mt][2] = As_l[r * 20 + kk + tg + 4];
            al[mt][3] = As_l[(r + 8) * 20 + kk + tg + 4];
        }
#pragma unroll
        for (int nt = 0; nt < NTL; nt++) {
            int r = wn + nt * 8 + gq;
            bh[nt][0] = Bs_h[r * 20 + kk + tg];
            bh[nt][1] = Bs_h[r * 20 + kk + tg + 4];
            bl[nt][0] = Bs_l[r * 20 + kk + tg];
            bl[nt][1] = Bs_l[r * 20 + kk + tg + 4];
        }
#pragma unroll
        for (int mt = 0; mt < MT; mt++)
#pragma unroll
            for (int nt = 0; nt < NTL; nt++) {
                float* a = acc + (mt * NTL + nt) * 4;
                mma16816(a, ah[mt], bh[nt]);
                mma16816(a, ah[mt], bl[nt]);
                mma16816(a, al[mt], bh[nt]);
            }
    }
}

// EPI: 0=store fp32 C, 1=LSTM, 2=relu->bf16 split dst, 3=decoder-3 y epilogue
template<int BM,int BN,int WM,int WN,int NTH,int EPI,int CI,bool RELU>
__global__ void __launch_bounds__(NTH) gemm(GArgs g)
{
    extern __shared__ char sm[];
    constexpr int MT = WM / 16, NTL = WN / 8, NWN = BN / WN;
    constexpr int stageB = (BM + BN) * 160;
    const int tid = threadIdx.x, warp = tid >> 5, lane = tid & 31;
    const int gq = lane >> 2, tg = lane & 3;
    const int wm = (warp / NWN) * WM, wn = (warp % NWN) * WN;
    const int bm = blockIdx.y * BM, bn = blockIdx.x * BN;
    const int K = g.K;

    float acc[MT * NTL * 4];
#pragma unroll
    for (int i = 0; i < MT * NTL * 4; i++) acc[i] = 0.f;

    const int nk = K >> 5;
    stage_load<BM,BN,NTH>(sm, tid, bm, bn, g.Ah, g.Al, g.lda, g.Bh, g.Bl, g.ldb, 0);
    for (int kt = 0; kt < nk; kt++) {
        if (kt + 1 < nk) {
            stage_load<BM,BN,NTH>(sm + ((kt + 1) & 1) * stageB, tid, bm, bn,
                                  g.Ah, g.Al, g.lda, g.Bh, g.Bl, g.ldb, (kt + 1) << 5);
            asm volatile("cp.async.wait_group 1;\n");
        } else {
            asm volatile("cp.async.wait_group 0;\n");
        }
        __syncthreads();
        stage_mma<BM,BN,MT,NTL>(sm + (kt & 1) * stageB, acc, wm, wn, gq, tg);
        __syncthreads();
    }

    if (EPI == 1) {
        float* tile = (float*)sm;
#pragma unroll
        for (int mt = 0; mt < MT; mt++)
#pragma unroll
            for (int nt = 0; nt < NTL; nt++) {
                int r0 = wm + mt * 16 + gq, c0 = wn + nt * 8 + 2 * tg;
                float* a = acc + (mt * NTL + nt) * 4;
                float v00 = a[0], v01 = a[1], v10 = a[2], v11 = a[3];
                if (CI == 2) {
                    const float* ci0 = g.Ci + (size_t)(bm + r0) * g.ldci + bn + c0;
                    const float* ci1 = g.Ci + (size_t)(bm + r0 + 8) * g.ldci + bn + c0;
                    v00 += ci0[0]; v01 += ci0[1]; v10 += ci1[0]; v11 += ci1[1];
                }
                tile[r0 * BN + c0] = v00; tile[r0 * BN + c0 + 1] = v01;
                tile[(r0 + 8) * BN + c0] = v10; tile[(r0 + 8) * BN + c0 + 1] = v11;
            }
        __syncthreads();
        for (int idx = tid; idx < BM * 32; idx += NTH) {
            int row = idx >> 5, w = idx & 31;
            float ig = tile[row * BN + w];
            float fg = tile[row * BN + 32 + w];
            float gg = tile[row * BN + 64 + w];
            float og = tile[row * BN + 96 + w];
            int b = bm + row, j = blockIdx.x * 32 + w;
            float si = 1.f / (1.f + expf(-ig));
            float sf = 1.f / (1.f + expf(-fg));
            float so = 1.f / (1.f + expf(-og));
            float cn = sf * g.cst[b * Hd + j] + si * tanhf(gg);
            float hn = so * tanhf(cn);
            g.cst[b * Hd + j] = cn;
            __nv_bfloat16 hh, hl, ch, cl;
            bsplit(hn, hh, hl); bsplit(cn, ch, cl);
            g.Xh[(size_t)b * XK + 320 + j] = hh;
            g.Xl[(size_t)b * XK + 320 + j] = hl;
            g.Ih[(size_t)b * IK + j] = ch;
            g.Il[(size_t)b * IK + j] = cl;
        }
        return;
    }

#pragma unroll
    for (int mt = 0; mt < MT; mt++)
#pragma unroll
        for (int nt = 0; nt < NTL; nt++) {
            float* a = acc + (mt * NTL + nt) * 4;
#pragma unroll
            for (int half = 0; half < 2; half++) {
                int r = bm + wm + mt * 16 + gq + half * 8;
                int c = bn + wn + nt * 8 + 2 * tg;
                float v0 = a[half * 2], v1 = a[half * 2 + 1];
                if (CI == 1) { v0 += g.Ci[c]; v1 += g.Ci[c + 1]; }
                else if (CI == 2) {
                    const float* ci = g.Ci + (size_t)r * g.ldci + c;
                    v0 += ci[0]; v1 += ci[1];
                }
                if (RELU) { v0 = fmaxf(v0, 0.f); v1 = fmaxf(v1, 0.f); }
                if (EPI == 0) {
                    *(float2*)&g.C[(size_t)r * g.ldc + c] = make_float2(v0, v1);
                } else if (EPI == 2) {
                    __nv_bfloat16 h0, l0, h1, l1;
                    bsplit(v0, h0, l0); bsplit(v1, h1, l1);
                    *(__nv_bfloat162*)&g.Dh[(size_t)r * g.ldd + c] = bmk2(h0, h1);
                    *(__nv_bfloat162*)&g.Dl[(size_t)r * g.ldd + c] = bmk2(l0, l1);
                } else if (EPI == 3) {
                    *(float2*)&g.fake[(size_t)r * (Td * Fd) + g.t * Fd + c] = make_float2(v0, v1);
                    __nv_bfloat162 oh = *(const __nv_bfloat162*)&g.XhR[(size_t)r * XK + 64 + c];
                    __nv_bfloat162 ol = *(const __nv_bfloat162*)&g.XlR[(size_t)r * XK + 64 + c];
                    *(__nv_bfloat162*)&g.Ih[(size_t)r * IK + 768 + c] = oh;
                    *(__nv_bfloat162*)&g.Il[(size_t)r * IK + 768 + c] = ol;
                    __nv_bfloat16 h0, l0, h1, l1;
                    bsplit(v0, h0, l0); bsplit(v1, h1, l1);
                    *(__nv_bfloat162*)&g.Ih[(size_t)r * IK + 512 + c] = bmk2(h0, h1);
                    *(__nv_bfloat162*)&g.Il[(size_t)r * IK + 512 + c] = bmk2(l0, l1);
                    *(__nv_bfloat162*)&g.Xh[(size_t)r * XK + 64 + c] = bmk2(h0, h1);
                    *(__nv_bfloat162*)&g.Xl[(size_t)r * XK + 64 + c] = bmk2(l0, l1);
                }
            }
        }
}

// ---------------- prep kernels ----------------
__device__ __forceinline__ int perm_n(int np) {
    int chunk = np >> 7, r = np & 127, gate = r >> 5, w = r & 31;
    return gate * 512 + chunk * 32 + w;
}

__global__ void prep_wcat(const float* __restrict__ Wx, const float* __restrict__ Wh) {
    size_t i = (size_t)blockIdx.x * blockDim.x + threadIdx.x;
    if (i >= (size_t)Gd * XK) return;
    int k = (int)(i % XK), np = (int)(i / XK);
    int n = perm_n(np);
    float v;
    if (k < 64)       v = Wx[(size_t)k * Gd + n];
    else if (k < 320) v = Wx[(size_t)(512 + k) * Gd + n];
    else              v = Wh[(size_t)(k - 320) * Gd + n];
    __nv_bfloat16 h, l; bsplit(v, h, l);
    g_WcatT_h[i] = h; g_WcatT_l[i] = l;
}

__global__ void prep_wxh(const float* __restrict__ Wx, const float* __restrict__ bl) {
    size_t i = (size_t)blockIdx.x * blockDim.x + threadIdx.x;
    if (i >= (size_t)Gd * Hd) return;
    int k = (int)(i % Hd), np = (int)(i / Hd);
    int n = perm_n(np);
    __nv_bfloat16 h, l; bsplit(Wx[(size_t)(64 + k) * Gd + n], h, l);
    g_WxhT_h[i] = h; g_WxhT_l[i] = l;
    if (k == 0) g_blstmp[np] = bl[n];
}

__global__ void prep_dec(const float* __restrict__ W1, const float* __restrict__ W2,
                         const float* __restrict__ W3) {
    size_t i = (size_t)blockIdx.x * blockDim.x + threadIdx.x;
    const size_t s1 = Fd * Hd, s2 = s1 + Fd * Fd, s3 = s2 + Fd * Fd;
    __nv_bfloat16 h, l;
    if (i < s1) {
        int k = (int)(i % Hd), n = (int)(i / Hd);
        bsplit(W1[(size_t)k * Fd + n], h, l);
        g_W1T_h[i] = h; g_W1T_l[i] = l;
    } else if (i < s2) {
        size_t j = i - s1; int k = (int)(j % Fd), n = (int)(j / Fd);
        bsplit(W2[(size_t)k * Fd + n], h, l);
        g_W2T_h[j] = h; g_W2T_l[j] = l;
    } else if (i < s3) {
        size_t j = i - s2; int k = (int)(j % Fd), n = (int)(j / Fd);
        bsplit(W3[(size_t)k * Fd + n], h, l);
        g_W3T_h[j] = h; g_W3T_l[j] = l;
    }
}

__global__ void prep_head(const float* __restrict__ W4, const float* __restrict__ W7,
                          const float* __restrict__ b4, const float* __restrict__ b7) {
    size_t i = (size_t)blockIdx.x * blockDim.x + threadIdx.x;
    const size_t s1 = 128 * IK, s2 = s1 + 128 * Hd;
    __nv_bfloat16 h, l;
    if (i < s1) {
        int k = (int)(i % IK), n = (int)(i / IK);
        float v;
        if (n < 64) v = W4[(size_t)(512 + k) * Zd + n];
        else {
            int n2 = n - 64;
            if (k < 512)      v = W7[(size_t)(512 + k) * Zd + n2];
            else if (k < 768) v = 0.f;
            else              v = W7[(size_t)(1024 + k - 768) * Zd + n2];
        }
        bsplit(v, h, l);
        g_WheadT_h[i] = h; g_WheadT_l[i] = l;
    } else if (i < s2) {
        size_t j = i - s1; int k = (int)(j % Hd), n = (int)(j / Hd);
        float v = (n < 64) ? W4[(size_t)k * Zd + n] : W7[(size_t)k * Zd + (n - 64)];
        bsplit(v, h, l);
        g_WbaseT_h[j] = h; g_WbaseT_l[j] = l;
        if (k == 0) g_bhz[n] = (n < 64) ? b4[n] : b7[n - 64];
    }
}

__global__ void prep_hi(const float* __restrict__ h_i) {
    size_t i = (size_t)blockIdx.x * blockDim.x + threadIdx.x;
    if (i >= (size_t)Bn * Hd) return;
    __nv_bfloat16 h, l; bsplit(h_i[i], h, l);
    g_hih[i] = h; g_hil[i] = l;
}

__global__ void zero_state() {
    size_t i = (size_t)blockIdx.x * blockDim.x + threadIdx.x;
    const size_t nx = (size_t)Bn * XK;
    if (i < nx) {
        __nv_bfloat16 z = __float2bfloat16(0.f);
        g_Xh0[i] = z; g_Xl0[i] = z; g_Xh1[i] = z; g_Xl1[i] = z;
        return;
    }
    i -= nx;
    if (i < (size_t)Bn * Hd) g_c[i] = 0.f;
}

__global__ void finish_both(int t,
    const float* __restrict__ W5, const float* __restrict__ b5,
    const float* __restrict__ W6, const float* __restrict__ b6,
    const float* __restrict__ W8, const float* __restrict__ b8,
    const float* __restrict__ W9, const float* __restrict__ b9,
    const float* __restrict__ eps_inf, const float* __restrict__ eps_pri,
    float* __restrict__ out_mean, float* __restrict__ out_lv, float* __restrict__ out_z,
    __nv_bfloat16* __restrict__ Xh, __nv_bfloat16* __restrict__ Xl)
{
    int idx = blockIdx.x * blockDim.x + threadIdx.x;
    if (idx >= Bn * Zd) return;
    int b = idx / Zd, z = idx % Zd;
    float m = b5[z], l = b6[z], mp = b8[z], lp = b9[z];
    const float* hz  = &g_hzc[b * 128];
    const float* hzp = hz + 64;
#pragma unroll 8
    for (int k = 0; k < Zd; k++) {
        float a = hz[k], ap = hzp[k];
        m  += a  * W5[k * Zd + z];
        l  += a  * W6[k * Zd + z];
        mp += ap * W8[k * Zd + z];
        lp += ap * W9[k * Zd + z];
    }
    m = fmaxf(m, 0.f); l = fmaxf(l, 0.f); mp = fmaxf(mp, 0.f); lp = fmaxf(lp, 0.f);
    float zi = m  + eps_inf[(size_t)t * Bn * Zd + idx] * sqrtf(expf(l));
    float zp = mp + eps_pri[(size_t)t * Bn * Zd + idx] * sqrtf(expf(lp));
    out_mean[(size_t)b * Td * Zd + (size_t)t * Zd + z] = m;
    out_lv  [(size_t)b * Td * Zd + (size_t)t * Zd + z] = l;
    out_z[(size_t)(2 * t)     * Bn * Zd + idx] = zi;
    out_z[(size_t)(2 * t + 1) * Bn * Zd + idx] = zp;
    __nv_bfloat16 zh, zl; bsplit(zi, zh, zl);
    Xh[(size_t)b * XK + z] = zh;
    Xl[(size_t)b * XK + z] = zl;
}

// ---------------- host ----------------
template<typename T> static T* sym(const void* s) { void* p = nullptr; cudaGetSymbolAddress(&p, s); return (T*)p; }

extern "C" void kernel_launch(void* const* d_in, const int* in_sizes, int n_in,
                              void* d_out, int out_size) {
    const float* h_i     = (const float*)d_in[0];
    const float* eps_inf = (const float*)d_in[1];
    const float* eps_pri = (const float*)d_in[2];
    const float* Wx      = (const float*)d_in[3];
    const float* Wh      = (const float*)d_in[4];
    const float* b_lstm  = (const float*)d_in[5];
    const float* W1 = (const float*)d_in[6],  *b1 = (const float*)d_in[7];
    const float* W2 = (const float*)d_in[8],  *b2 = (const float*)d_in[9];
    const float* W3 = (const float*)d_in[10], *b3 = (const float*)d_in[11];
    const float* W4 = (const float*)d_in[12], *b4 = (const float*)d_in[13];
    const float* W5 = (const float*)d_in[14], *b5 = (const float*)d_in[15];
    const float* W6 = (const float*)d_in[16], *b6 = (const float*)d_in[17];
    const float* W7 = (const float*)d_in[18], *b7 = (const float*)d_in[19];
    const float* W8 = (const float*)d_in[20], *b8 = (const float*)d_in[21];
    const float* W9 = (const float*)d_in[22], *b9 = (const float*)d_in[23];

    float* out      = (float*)d_out;
    float* out_fake = out;
    float* out_mean = out_fake + (size_t)Bn * Td * Fd;
    float* out_lv   = out_mean + (size_t)Bn * Td * Zd;
    float* out_z    = out_lv   + (size_t)Bn * Td * Zd;

    __nv_bfloat16* Xh0 = sym<__nv_bfloat16>(g_Xh0); __nv_bfloat16* Xl0 = sym<__nv_bfloat16>(g_Xl0);
    __nv_bfloat16* Xh1 = sym<__nv_bfloat16>(g_Xh1); __nv_bfloat16* Xl1 = sym<__nv_bfloat16>(g_Xl1);

    GArgs a{};
    a.cst = sym<float>(g_c);
    a.Ih = sym<__nv_bfloat16>(g_Ih); a.Il = sym<__nv_bfloat16>(g_Il);

    float* pBaseg  = sym<float>(g_baseg);
    float* pGates0 = sym<float>(g_gates0);
    float* pGates1 = sym<float>(g_gates1);
    float* pBasehz = sym<float>(g_basehz);
    float* pHzc    = sym<float>(g_hzc);
    float* pBlstmp = sym<float>(g_blstmp);
    float* pBhz    = sym<float>(g_bhz);

    constexpr int SM128128 = (128 + 128) * 160 * 2;   // 81920
    constexpr int SM6464   = (64 + 64) * 160 * 2;     // 40960
    cudaFuncSetAttribute(gemm<128,128,64,32,256,0,1,false>, cudaFuncAttributeMaxDynamicSharedMemorySize, SM128128);
    cudaFuncSetAttribute(gemm<128,128,64,32,256,0,2,false>, cudaFuncAttributeMaxDynamicSharedMemorySize, SM128128);
    cudaFuncSetAttribute(gemm<128,128,64,32,256,1,2,false>, cudaFuncAttributeMaxDynamicSharedMemorySize, SM128128);
    cudaFuncSetAttribute(gemm<64,64,32,32,128,2,1,true>,    cudaFuncAttributeMaxDynamicSharedMemorySize, SM6464);
    cudaFuncSetAttribute(gemm<64,64,32,32,128,3,1,true>,    cudaFuncAttributeMaxDynamicSharedMemorySize, SM6464);
    cudaFuncSetAttribute(gemm<64,64,32,32,128,0,2,true>,    cudaFuncAttributeMaxDynamicSharedMemorySize, SM6464);
    cudaFuncSetAttribute(gemm<64,64,32,32,128,0,1,false>,   cudaFuncAttributeMaxDynamicSharedMemorySize, SM6464);

    // second stream + events (created once; capture-fork pattern)
    static cudaStream_t s2 = nullptr;
    static cudaEvent_t evFork = nullptr, evL = nullptr, evB = nullptr;
    if (!s2) {
        cudaStreamCreateWithFlags(&s2, cudaStreamNonBlocking);
        cudaEventCreateWithFlags(&evFork, cudaEventDisableTiming);
        cudaEventCreateWithFlags(&evL, cudaEventDisableTiming);
        cudaEventCreateWithFlags(&evB, cudaEventDisableTiming);
    }

    // ---- init (main stream) ----
    {
        size_t n = (size_t)Bn * XK + (size_t)Bn * Hd;
        zero_state<<<(unsigned)((n + 255) / 256), 256>>>();
        prep_wcat<<<(unsigned)(((size_t)Gd * XK + 255) / 256), 256>>>(Wx, Wh);
        prep_wxh<<<(unsigned)(((size_t)Gd * Hd + 255) / 256), 256>>>(Wx, b_lstm);
        prep_dec<<<(unsigned)(((size_t)Fd * Hd + 2 * Fd * Fd + 255) / 256), 256>>>(W1, W2, W3);
        prep_head<<<(unsigned)((128 * (IK + Hd) + 255) / 256), 256>>>(W4, W7, b4, b7);
        prep_hi<<<(unsigned)(((size_t)Bn * Hd + 255) / 256), 256>>>(h_i);
    }

    // ---- hoisted base GEMMs ----
    {
        GArgs b = a;
        b.Ah = sym<__nv_bfloat16>(g_hih); b.Al = sym<__nv_bfloat16>(g_hil); b.lda = Hd;
        b.Bh = sym<__nv_bfloat16>(g_WxhT_h); b.Bl = sym<__nv_bfloat16>(g_WxhT_l); b.ldb = Hd;
        b.Ci = pBlstmp; b.C = pBaseg; b.ldc = Gd; b.K = Hd;
        gemm<128,128,64,32,256,0,1,false><<<dim3(16, 32), 256, SM128128>>>(b);

        b.Bh = sym<__nv_bfloat16>(g_WbaseT_h); b.Bl = sym<__nv_bfloat16>(g_WbaseT_l); b.ldb = Hd;
        b.Ci = pBhz; b.C = pBasehz; b.ldc = 128; b.K = Hd;
        gemm<64,64,32,32,128,0,1,false><<<dim3(2, 64), 128, SM6464>>>(b);
    }

    // fork: gate_h_0 on s2 (h0 = 0 -> partial0 = baseg)
    cudaEventRecord(evFork, 0);
    cudaStreamWaitEvent(s2, evFork, 0);
    {
        GArgs b = a;
        b.Ah = Xh0 + 320; b.Al = Xl0 + 320; b.lda = XK;
        b.Bh = sym<__nv_bfloat16>(g_WcatT_h) + 320; b.Bl = sym<__nv_bfloat16>(g_WcatT_l) + 320; b.ldb = XK;
        b.Ci = pBaseg; b.ldci = Gd; b.C = pGates0; b.ldc = Gd; b.K = Hd;
        gemm<128,128,64,32,256,0,2,false><<<dim3(16, 32), 256, SM128128, s2>>>(b);
    }
    cudaEventRecord(evB, s2);

    for (int t = 0; t < Td; t++) {
        __nv_bfloat16* XrH = (t & 1) ? Xh1 : Xh0;  // state entering step t
        __nv_bfloat16* XrL = (t & 1) ? Xl1 : Xl0;
        __nv_bfloat16* XwH = (t & 1) ? Xh0 : Xh1;  // state leaving step t
        __nv_bfloat16* XwL = (t & 1) ? Xl0 : Xl1;
        float* pPart  = (t & 1) ? pGates1 : pGates0;
        float* pPartN = (t & 1) ? pGates0 : pGates1;

        // wait for gate_h_t (partial ready), then gate_zy + fused LSTM
        cudaStreamWaitEvent(0, evB, 0);
        {
            GArgs b = a;
            b.Ah = XrH; b.Al = XrL; b.lda = XK;
            b.Bh = sym<__nv_bfloat16>(g_WcatT_h); b.Bl = sym<__nv_bfloat16>(g_WcatT_l); b.ldb = XK;
            b.Ci = pPart; b.ldci = Gd; b.K = 320;
            b.Xh = XwH; b.Xl = XwL;
            gemm<128,128,64,32,256,1,2,false><<<dim3(16, 32), 256, SM128128>>>(b);
        }

        // launch next step's gate_h on s2 (reads h_t just written into Xw)
        if (t + 1 < Td) {
            cudaEventRecord(evL, 0);
            cudaStreamWaitEvent(s2, evL, 0);
            GArgs b = a;
            b.Ah = XwH + 320; b.Al = XwL + 320; b.lda = XK;
            b.Bh = sym<__nv_bfloat16>(g_WcatT_h) + 320; b.Bl = sym<__nv_bfloat16>(g_WcatT_l) + 320; b.ldb = XK;
            b.Ci = pBaseg; b.ldci = Gd; b.C = pPartN; b.ldc = Gd; b.K = Hd;
            gemm<128,128,64,32,256,0,2,false><<<dim3(16, 32), 256, SM128128, s2>>>(b);
            cudaEventRecord(evB, s2);
        }

        // decoder MLP (reads new h from Xw; concurrent with gate_h on s2)
        {
            GArgs b = a;
            b.Ah = XwH + 320; b.Al = XwL + 320; b.lda = XK;
            b.Bh = sym<__nv_bfloat16>(g_W1T_h); b.Bl = sym<__nv_bfloat16>(g_W1T_l); b.ldb = Hd;
            b.Ci = b1; b.K = Hd;
            b.Dh = sym<__nv_bfloat16>(g_t1h); b.Dl = sym<__nv_bfloat16>(g_t1l); b.ldd = Fd;
            gemm<64,64,32,32,128,2,1,true><<<dim3(4, 64), 128, SM6464>>>(b);

            b.Ah = sym<__nv_bfloat16>(g_t1h); b.Al = sym<__nv_bfloat16>(g_t1l); b.lda = Fd;
            b.Bh = sym<__nv_bfloat16>(g_W2T_h); b.Bl = sym<__nv_bfloat16>(g_W2T_l); b.ldb = Fd;
            b.Ci = b2; b.K = Fd;
            b.Dh = sym<__nv_bfloat16>(g_t2h); b.Dl = sym<__nv_bfloat16>(g_t2l);
            gemm<64,64,32,32,128,2,1,true><<<dim3(4, 64), 128, SM6464>>>(b);

            b.Ah = sym<__nv_bfloat16>(g_t2h); b.Al = sym<__nv_bfloat16>(g_t2l); b.lda = Fd;
            b.Bh = sym<__nv_bfloat16>(g_W3T_h); b.Bl = sym<__nv_bfloat16>(g_W3T_l); b.ldb = Fd;
            b.Ci = b3; b.K = Fd;
            b.fake = out_fake; b.t = t;
            b.XhR = XrH; b.XlR = XrL;
            b.Xh  = XwH; b.Xl  = XwL;
            gemm<64,64,32,32,128,3,1,true><<<dim3(4, 64), 128, SM6464>>>(b);
        }
        // merged heads
        {
            GArgs b = a;
            b.Ah = a.Ih; b.Al = a.Il; b.lda = IK;
            b.Bh = sym<__nv_bfloat16>(g_WheadT_h); b.Bl = sym<__nv_bfloat16>(g_WheadT_l); b.ldb = IK;
            b.Ci = pBasehz; b.ldci = 128; b.C = pHzc; b.ldc = 128; b.K = IK;
            gemm<64,64,32,32,128,0,2,true><<<dim3(2, 64), 128, SM6464>>>(b);
        }
        finish_both<<<(Bn * Zd + 255) / 256, 256>>>(t, W5, b5, W6, b6, W8, b8, W9, b9,
                                                    eps_inf, eps_pri, out_mean, out_lv, out_z,
                                                    XwH, XwL);
    }
}

// round 6
// speedup vs baseline: 1.0679x; 1.0679x over previous
#include <cuda_runtime.h>
#include <cuda_bf16.h>
#include <math.h>
#include <stdint.h>

#define Bn   4096
#define Hd   512
#define Fd   256
#define Zd   64
#define Td   16
#define Gd   2048
#define XK   832      // bf16 X row: [z(64) | y(256) | h(512)]
#define IK   1024     // head K:     [c(512) | y_j(256) | y_prev(256)]
#define CK   512      // c buffer row

// ---------------- persistent buffers ----------------
__device__ float g_baseg [(size_t)Bn * Gd];    // permuted layout
__device__ float g_basehz[Bn * 128];           // [base4 | base7]
__device__ float g_c     [Bn * Hd];
__device__ float g_blstmp[Gd];
__device__ float g_bhz   [128];

// double-buffered state X
__device__ __nv_bfloat16 g_Xh0[(size_t)Bn * XK], g_Xl0[(size_t)Bn * XK];
__device__ __nv_bfloat16 g_Xh1[(size_t)Bn * XK], g_Xl1[(size_t)Bn * XK];
__device__ __nv_bfloat16 g_Ch [(size_t)Bn * CK], g_Cl [(size_t)Bn * CK];  // cell state bf16 hi/lo
__device__ __nv_bfloat16 g_hih[(size_t)Bn * Hd], g_hil[(size_t)Bn * Hd];

// weights: n-major [N][K] bf16 hi/lo
__device__ __nv_bfloat16 g_WcatT_h[(size_t)Gd * XK], g_WcatT_l[(size_t)Gd * XK];
__device__ __nv_bfloat16 g_WxhT_h [(size_t)Gd * Hd], g_WxhT_l [(size_t)Gd * Hd];
__device__ __nv_bfloat16 g_W1T_h  [Fd * Hd], g_W1T_l  [Fd * Hd];
__device__ __nv_bfloat16 g_W2T_h  [Fd * Fd], g_W2T_l  [Fd * Fd];
__device__ __nv_bfloat16 g_W3T_h  [Fd * Fd], g_W3T_l  [Fd * Fd];
__device__ __nv_bfloat16 g_WheadT_h[128 * IK], g_WheadT_l[128 * IK];
__device__ __nv_bfloat16 g_WbaseT_h[128 * Hd], g_WbaseT_l[128 * Hd];

// ---------------- helpers ----------------
__device__ __forceinline__ void bsplit(float v, __nv_bfloat16& h, __nv_bfloat16& l) {
    h = __float2bfloat16_rn(v);
    l = __float2bfloat16_rn(v - __bfloat162float(h));
}
__device__ __forceinline__ uint32_t bpack(__nv_bfloat16 a, __nv_bfloat16 b) {
    __nv_bfloat162 t; t.x = a; t.y = b;
    return reinterpret_cast<uint32_t&>(t);
}
__device__ __forceinline__ __nv_bfloat162 bmk2(__nv_bfloat16 a, __nv_bfloat16 b) {
    __nv_bfloat162 t; t.x = a; t.y = b; return t;
}
__device__ __forceinline__ void mma16816(float* c, const uint32_t* a, const uint32_t* b) {
    asm volatile(
        "mma.sync.aligned.m16n8k16.row.col.f32.bf16.bf16.f32 "
        "{%0,%1,%2,%3}, {%4,%5,%6,%7}, {%8,%9}, {%0,%1,%2,%3};\n"
        : "+f"(c[0]), "+f"(c[1]), "+f"(c[2]), "+f"(c[3])
        : "r"(a[0]), "r"(a[1]), "r"(a[2]), "r"(a[3]), "r"(b[0]), "r"(b[1]));
}
__device__ __forceinline__ void cpa16(void* dst, const void* src) {
    uint32_t d = (uint32_t)__cvta_generic_to_shared(dst);
    asm volatile("cp.async.cg.shared.global [%0], [%1], 16;\n" :: "r"(d), "l"(src));
}
#define CPA_COMMIT() asm volatile("cp.async.commit_group;\n")
#define CPA_WAIT1()  asm volatile("cp.async.wait_group 1;\n")
#define CPA_WAIT0()  asm volatile("cp.async.wait_group 0;\n")

// generic mma on one 32-K stage; A hi at Ab, lo at Ab+AHS; B hi at Bb, lo at Bb+BHS
template<int MT,int NTL,int AHS,int BHS>
__device__ __forceinline__ void stage_mma2(const char* Ab, const char* Bb, float* acc,
                                           int wm, int wn, int gq, int tg)
{
    const uint32_t* As_h = (const uint32_t*)Ab;
    const uint32_t* As_l = (const uint32_t*)(Ab + AHS);
    const uint32_t* Bs_h = (const uint32_t*)Bb;
    const uint32_t* Bs_l = (const uint32_t*)(Bb + BHS);
#pragma unroll
    for (int kk = 0; kk < 16; kk += 8) {
        uint32_t ah[MT][4], al[MT][4], bh[NTL][2], bl[NTL][2];
#pragma unroll
        for (int mt = 0; mt < MT; mt++) {
            int r = wm + mt * 16 + gq;
            ah[mt][0] = As_h[r * 20 + kk + tg];
            ah[mt][1] = As_h[(r + 8) * 20 + kk + tg];
            ah[mt][2] = As_h[r * 20 + kk + tg + 4];
            ah[mt][3] = As_h[(r + 8) * 20 + kk + tg + 4];
            al[mt][0] = As_l[r * 20 + kk + tg];
            al[mt][1] = As_l[(r + 8) * 20 + kk + tg];
            al[mt][2] = As_l[r * 20 + kk + tg + 4];
            al[mt][3] = As_l[(r + 8) * 20 + kk + tg + 4];
        }
#pragma unroll
        for (int nt = 0; nt < NTL; nt++) {
            int r = wn + nt * 8 + gq;
            bh[nt][0] = Bs_h[r * 20 + kk + tg];
            bh[nt][1] = Bs_h[r * 20 + kk + tg + 4];
            bl[nt][0] = Bs_l[r * 20 + kk + tg];
            bl[nt][1] = Bs_l[r * 20 + kk + tg + 4];
        }
#pragma unroll
        for (int mt = 0; mt < MT; mt++)
#pragma unroll
            for (int nt = 0; nt < NTL; nt++) {
                float* a = acc + (mt * NTL + nt) * 4;
                mma16816(a, ah[mt], bh[nt]);
                mma16816(a, ah[mt], bl[nt]);
                mma16816(a, al[mt], bh[nt]);
            }
    }
}

// ================= gate GEMM (+fused LSTM) =================
struct GArgs {
    const __nv_bfloat16 *Ah, *Al; int lda;
    const __nv_bfloat16 *Bh, *Bl; int ldb;
    const float* Ci; int ldci;
    float* C; int ldc;
    int K;
    float* cst;
    __nv_bfloat16 *Xh, *Xl;       // write h (next-state buffer)
    __nv_bfloat16 *Ch, *Cl;       // write c bf16
};

template<int BM,int BN,int NTH>
__device__ __forceinline__ void stage_load(char* base, int tid, int bm, int bn,
    const __nv_bfloat16* Ah, const __nv_bfloat16* Al, int lda,
    const __nv_bfloat16* Bh, const __nv_bfloat16* Bl, int ldb, int k0)
{
#pragma unroll
    for (int i = tid; i < BM * 4; i += NTH) {
        int row = i >> 2, c4 = (i & 3) * 16;
        size_t off = ((size_t)(bm + row) * lda + k0) * 2 + c4;
        cpa16(base + row * 80 + c4, (const char*)Ah + off);
        cpa16(base + BM * 80 + row * 80 + c4, (const char*)Al + off);
    }
#pragma unroll
    for (int i = tid; i < BN * 4; i += NTH) {
        int row = i >> 2, c4 = (i & 3) * 16;
        size_t off = ((size_t)(bn + row) * ldb + k0) * 2 + c4;
        cpa16(base + BM * 160 + row * 80 + c4, (const char*)Bh + off);
        cpa16(base + BM * 160 + BN * 80 + row * 80 + c4, (const char*)Bl + off);
    }
    CPA_COMMIT();
}

// EPI: 0=store fp32 C (+bias), 1=LSTM epilogue
template<int BM,int BN,int WM,int WN,int NTH,int EPI,int CI>
__global__ void __launch_bounds__(NTH) gemm(GArgs g)
{
    extern __shared__ char sm[];
    constexpr int MT = WM / 16, NTL = WN / 8, NWN = BN / WN;
    constexpr int stageB = (BM + BN) * 160;
    const int tid = threadIdx.x, warp = tid >> 5, lane = tid & 31;
    const int gq = lane >> 2, tg = lane & 3;
    const int wm = (warp / NWN) * WM, wn = (warp % NWN) * WN;
    const int bm = blockIdx.y * BM, bn = blockIdx.x * BN;
    const int K = g.K;

    float acc[MT * NTL * 4];
#pragma unroll
    for (int i = 0; i < MT * NTL * 4; i++) acc[i] = 0.f;

    const int nk = K >> 5;
    stage_load<BM,BN,NTH>(sm, tid, bm, bn, g.Ah, g.Al, g.lda, g.Bh, g.Bl, g.ldb, 0);
    for (int kt = 0; kt < nk; kt++) {
        if (kt + 1 < nk) {
            stage_load<BM,BN,NTH>(sm + ((kt + 1) & 1) * stageB, tid, bm, bn,
                                  g.Ah, g.Al, g.lda, g.Bh, g.Bl, g.ldb, (kt + 1) << 5);
            CPA_WAIT1();
        } else {
            CPA_WAIT0();
        }
        __syncthreads();
        const char* cur = sm + (kt & 1) * stageB;
        stage_mma2<MT,NTL,BM*80,BN*80>(cur, cur + BM * 160, acc, wm, wn, gq, tg);
        __syncthreads();
    }

    if (EPI == 1) {
        float* tile = (float*)sm;
#pragma unroll
        for (int mt = 0; mt < MT; mt++)
#pragma unroll
            for (int nt = 0; nt < NTL; nt++) {
                int r0 = wm + mt * 16 + gq, c0 = wn + nt * 8 + 2 * tg;
                float* a = acc + (mt * NTL + nt) * 4;
                const float* ci0 = g.Ci + (size_t)(bm + r0) * g.ldci + bn + c0;
                const float* ci1 = g.Ci + (size_t)(bm + r0 + 8) * g.ldci + bn + c0;
                tile[r0 * BN + c0]           = a[0] + ci0[0];
                tile[r0 * BN + c0 + 1]       = a[1] + ci0[1];
                tile[(r0 + 8) * BN + c0]     = a[2] + ci1[0];
                tile[(r0 + 8) * BN + c0 + 1] = a[3] + ci1[1];
            }
        __syncthreads();
        for (int idx = tid; idx < BM * 32; idx += NTH) {
            int row = idx >> 5, w = idx & 31;
            float ig = tile[row * BN + w];
            float fg = tile[row * BN + 32 + w];
            float gg = tile[row * BN + 64 + w];
            float og = tile[row * BN + 96 + w];
            int b = bm + row, j = blockIdx.x * 32 + w;
            float si = 1.f / (1.f + expf(-ig));
            float sf = 1.f / (1.f + expf(-fg));
            float so = 1.f / (1.f + expf(-og));
            float cn = sf * g.cst[b * Hd + j] + si * tanhf(gg);
            float hn = so * tanhf(cn);
            g.cst[b * Hd + j] = cn;
            __nv_bfloat16 hh, hl, ch, cl;
            bsplit(hn, hh, hl); bsplit(cn, ch, cl);
            g.Xh[(size_t)b * XK + 320 + j] = hh;
            g.Xl[(size_t)b * XK + 320 + j] = hl;
            g.Ch[(size_t)b * CK + j] = ch;
            g.Cl[(size_t)b * CK + j] = cl;
        }
        return;
    }

    // EPI==0: fp32 store (+ bias row)
#pragma unroll
    for (int mt = 0; mt < MT; mt++)
#pragma unroll
        for (int nt = 0; nt < NTL; nt++) {
            float* a = acc + (mt * NTL + nt) * 4;
#pragma unroll
            for (int half = 0; half < 2; half++) {
                int r = bm + wm + mt * 16 + gq + half * 8;
                int c = bn + wn + nt * 8 + 2 * tg;
                float v0 = a[half * 2], v1 = a[half * 2 + 1];
                if (CI == 1) { v0 += g.Ci[c]; v1 += g.Ci[c + 1]; }
                *(float2*)&g.C[(size_t)r * g.ldc + c] = make_float2(v0, v1);
            }
        }
}

// ================= fused tail kernel =================
// One block = 32 batch rows through dec1->dec2->dec3->head->finish.
// smem arena (174080 B):
//   [0,      92160)  GEMM stage double-buffers (dec stage = 5120 A + 40960 B)
//   [92160, 133120)  tA: t1 chunks / later y_j chunks (8 x 5120)
//   [133120,174080)  tB: t2 chunks / later hzc fp32 (32 x 130)
struct TailArgs {
    const __nv_bfloat16 *XwH, *XwL;      // current state (h fresh)
    __nv_bfloat16 *XwHm, *XwLm;          // mutable (write y, z)
    const __nv_bfloat16 *XrH, *XrL;      // previous state (y_prev)
    const __nv_bfloat16 *Ch, *Cl;        // cell state bf16
    const float* basehz;
    const float *b1, *b2, *b3;
    const float *W5, *b5, *W6, *b6, *W8, *b8, *W9, *b9;
    const float *eps_inf, *eps_pri;
    float *fake, *out_mean, *out_lv, *out_z;
    int t;
};

template<int BN>
__device__ __forceinline__ void tail_loadB(char* st, int tid,
    const __nv_bfloat16* Bh, const __nv_bfloat16* Bl, int ldb, int kg)
{
#pragma unroll
    for (int i = tid; i < BN * 4; i += 128) {
        int row = i >> 2, c4 = (i & 3) * 16;
        size_t off = ((size_t)row * ldb + kg) * 2 + c4;
        cpa16(st + row * 80 + c4, (const char*)Bh + off);
        cpa16(st + BN * 80 + row * 80 + c4, (const char*)Bl + off);
    }
}

__device__ __forceinline__ void tail_loadA(char* st, int arow, int ac4, int r0,
    const __nv_bfloat16* Ah, const __nv_bfloat16* Al, int lda, int kg)
{
    size_t off = ((size_t)(r0 + arow) * lda + kg) * 2 + ac4;
    cpa16(st + arow * 80 + ac4, (const char*)Ah + off);
    cpa16(st + 2560 + arow * 80 + ac4, (const char*)Al + off);
}

// write relu(acc+bias) -> chunked bf16 hi/lo A-layout (chunk stride 5120, lo at +2560)
template<int NTL>
__device__ __forceinline__ void epi_chunk(const float* acc, const float* bias,
                                          char* dst, int wn, int gq, int tg)
{
#pragma unroll
    for (int mt = 0; mt < 2; mt++)
#pragma unroll
        for (int nt = 0; nt < NTL; nt++)
#pragma unroll
            for (int half = 0; half < 2; half++) {
                int row = mt * 16 + gq + half * 8;
                int col = wn + nt * 8 + 2 * tg;
                const float* a = acc + (mt * NTL + nt) * 4 + half * 2;
                float v0 = fmaxf(a[0] + bias[col], 0.f);
                float v1 = fmaxf(a[1] + bias[col + 1], 0.f);
                __nv_bfloat16 h0, l0, h1, l1;
                bsplit(v0, h0, l0); bsplit(v1, h1, l1);
                char* cb = dst + (col >> 5) * 5120;
                int kp = (col & 31) >> 1;
                ((uint32_t*)cb)[row * 20 + kp] = bpack(h0, h1);
                ((uint32_t*)(cb + 2560))[row * 20 + kp] = bpack(l0, l1);
            }
}

__global__ void __launch_bounds__(128) tail_kernel(TailArgs g)
{
    extern __shared__ char sm[];
    char* stages = sm;
    char* tA = sm + 92160;
    char* tB = sm + 133120;
    float* hzc = (float*)tB;     // 32 x 130 fp32, aliases tB after dec3

    const int tid = threadIdx.x, lane = tid & 31, warp = tid >> 5;
    const int gq = lane >> 2, tg = lane & 3;
    const int r0 = blockIdx.x * 32;
    const int arow = tid >> 2, ac4 = (tid & 3) * 16;
    constexpr int DST = 46080;   // dec stage size
    constexpr int HST = 25600;   // head stage size

    // ---------- dec1: t1 = relu(h @ W1 + b1)  K=512, BN=256 ----------
    {
        float acc[64];
#pragma unroll
        for (int i = 0; i < 64; i++) acc[i] = 0.f;
        tail_loadA(stages, arow, ac4, r0, g.XwH + 320, g.XwL + 320, XK, 0);
        tail_loadB<256>(stages + 5120, tid, g_W1T_h, g_W1T_l, Hd, 0);
        CPA_COMMIT();
        for (int kt = 0; kt < 16; kt++) {
            char* cur = stages + (kt & 1) * DST;
            if (kt < 15) {
                char* nxt = stages + ((kt + 1) & 1) * DST;
                tail_loadA(nxt, arow, ac4, r0, g.XwH + 320, g.XwL + 320, XK, (kt + 1) * 32);
                tail_loadB<256>(nxt + 5120, tid, g_W1T_h, g_W1T_l, Hd, (kt + 1) * 32);
                CPA_COMMIT(); CPA_WAIT1();
            } else CPA_WAIT0();
            __syncthreads();
            stage_mma2<2,8,2560,20480>(cur, cur + 5120, acc, 0, warp * 64, gq, tg);
            __syncthreads();
        }
        epi_chunk<8>(acc, g.b1, tA, warp * 64, gq, tg);
        __syncthreads();
    }
    // ---------- dec2: t2 = relu(t1 @ W2 + b2)  K=256 local ----------
    {
        float acc[64];
#pragma unroll
        for (int i = 0; i < 64; i++) acc[i] = 0.f;
        tail_loadB<256>(stages + 5120, tid, g_W2T_h, g_W2T_l, Fd, 0);
        CPA_COMMIT();
        for (int kt = 0; kt < 8; kt++) {
            char* cur = stages + (kt & 1) * DST;
            if (kt < 7) {
                tail_loadB<256>(stages + ((kt + 1) & 1) * DST + 5120, tid,
                                g_W2T_h, g_W2T_l, Fd, (kt + 1) * 32);
                CPA_COMMIT(); CPA_WAIT1();
            } else CPA_WAIT0();
            __syncthreads();
            stage_mma2<2,8,2560,20480>(tA + kt * 5120, cur + 5120, acc, 0, warp * 64, gq, tg);
            __syncthreads();
        }
        epi_chunk<8>(acc, g.b2, tB, warp * 64, gq, tg);
        __syncthreads();
    }
    // ---------- dec3: y = relu(t2 @ W3 + b3) -> fake, Xw y, yj(local) ----------
    {
        float acc[64];
#pragma unroll
        for (int i = 0; i < 64; i++) acc[i] = 0.f;
        tail_loadB<256>(stages + 5120, tid, g_W3T_h, g_W3T_l, Fd, 0);
        CPA_COMMIT();
        for (int kt = 0; kt < 8; kt++) {
            char* cur = stages + (kt & 1) * DST;
            if (kt < 7) {
                tail_loadB<256>(stages + ((kt + 1) & 1) * DST + 5120, tid,
                                g_W3T_h, g_W3T_l, Fd, (kt + 1) * 32);
                CPA_COMMIT(); CPA_WAIT1();
            } else CPA_WAIT0();
            __syncthreads();
            stage_mma2<2,8,2560,20480>(tB + kt * 5120, cur + 5120, acc, 0, warp * 64, gq, tg);
            __syncthreads();
        }
        // custom epilogue: out_fake fp32, new y -> Xw, y_j -> tA chunks
#pragma unroll
        for (int mt = 0; mt < 2; mt++)
#pragma unroll
            for (int nt = 0; nt < 8; nt++)
#pragma unroll
                for (int half = 0; half < 2; half++) {
                    int row = mt * 16 + gq + half * 8;
                    int col = warp * 64 + nt * 8 + 2 * tg;
                    int b = r0 + row;
                    const float* a = acc + (mt * 8 + nt) * 4 + half * 2;
                    float v0 = fmaxf(a[0] + g.b3[col], 0.f);
                    float v1 = fmaxf(a[1] + g.b3[col + 1], 0.f);
                    *(float2*)&g.fake[(size_t)b * (Td * Fd) + g.t * Fd + col] = make_float2(v0, v1);
                    __nv_bfloat16 h0, l0, h1, l1;
                    bsplit(v0, h0, l0); bsplit(v1, h1, l1);
                    *(__nv_bfloat162*)&g.XwHm[(size_t)b * XK + 64 + col] = bmk2(h0, h1);
                    *(__nv_bfloat162*)&g.XwLm[(size_t)b * XK + 64 + col] = bmk2(l0, l1);
                    char* cb = tA + (col >> 5) * 5120;
                    int kp = (col & 31) >> 1;
                    ((uint32_t*)cb)[row * 20 + kp] = bpack(h0, h1);
                    ((uint32_t*)(cb + 2560))[row * 20 + kp] = bpack(l0, l1);
                }
        __syncthreads();
    }
    // ---------- head: [hz|hzp] = relu(I @ Whead + basehz)  K=1024, BN=128 ----------
    {
        float acc[32];
#pragma unroll
        for (int i = 0; i < 32; i++) acc[i] = 0.f;
        // chunk sources: 0..15 c (global), 16..23 y_j (local tA), 24..31 y_prev (global Xr)
        tail_loadA(stages, arow, ac4, r0, g.Ch, g.Cl, CK, 0);
        tail_loadB<128>(stages + 5120, tid, g_WheadT_h, g_WheadT_l, IK, 0);
        CPA_COMMIT();
        for (int kt = 0; kt < 32; kt++) {
            char* cur = stages + (kt & 1) * HST;
            if (kt < 31) {
                char* nxt = stages + ((kt + 1) & 1) * HST;
                int kn = kt + 1;
                if (kn < 16)       tail_loadA(nxt, arow, ac4, r0, g.Ch, g.Cl, CK, kn * 32);
                else if (kn >= 24) tail_loadA(nxt, arow, ac4, r0, g.XrH, g.XrL, XK, 64 + (kn - 24) * 32);
                tail_loadB<128>(nxt + 5120, tid, g_WheadT_h, g_WheadT_l, IK, kn * 32);
                CPA_COMMIT(); CPA_WAIT1();
            } else CPA_WAIT0();
            __syncthreads();
            const char* Ab = (kt >= 16 && kt < 24) ? (tA + (kt - 16) * 5120) : cur;
            stage_mma2<2,4,2560,10240>(Ab, cur + 5120, acc, 0, warp * 32, gq, tg);
            __syncthreads();
        }
        // epilogue -> hzc smem (stride 130 floats)
#pragma unroll
        for (int mt = 0; mt < 2; mt++)
#pragma unroll
            for (int nt = 0; nt < 4; nt++)
#pragma unroll
                for (int half = 0; half < 2; half++) {
                    int row = mt * 16 + gq + half * 8;
                    int col = warp * 32 + nt * 8 + 2 * tg;
                    const float* a = acc + (mt * 4 + nt) * 4 + half * 2;
                    const float* bz = g.basehz + (size_t)(r0 + row) * 128 + col;
                    hzc[row * 130 + col]     = fmaxf(a[0] + bz[0], 0.f);
                    hzc[row * 130 + col + 1] = fmaxf(a[1] + bz[1], 0.f);
                }
        __syncthreads();
    }
    // ---------- finish: z5/z6/z8/z9 (K=64) + reparam + state z ----------
    for (int idx = tid; idx < 32 * 64; idx += 128) {
        int row = idx >> 6, z = idx & 63, b = r0 + row;
        float m = g.b5[z], l = g.b6[z], mp = g.b8[z], lp = g.b9[z];
        const float* hz = &hzc[row * 130];
#pragma unroll 8
        for (int k = 0; k < 64; k++) {
            float av = hz[k], ap = hz[64 + k];
            m  += av * g.W5[k * Zd + z];
            l  += av * g.W6[k * Zd + z];
            mp += ap * g.W8[k * Zd + z];
            lp += ap * g.W9[k * Zd + z];
        }
        m = fmaxf(m, 0.f); l = fmaxf(l, 0.f); mp = fmaxf(mp, 0.f); lp = fmaxf(lp, 0.f);
        size_t gi = (size_t)b * Zd + z;
        float zi = m  + g.eps_inf[(size_t)g.t * Bn * Zd + gi] * sqrtf(expf(l));
        float zp = mp + g.eps_pri[(size_t)g.t * Bn * Zd + gi] * sqrtf(expf(lp));
        g.out_mean[(size_t)b * Td * Zd + (size_t)g.t * Zd + z] = m;
        g.out_lv  [(size_t)b * Td * Zd + (size_t)g.t * Zd + z] = l;
        g.out_z[(size_t)(2 * g.t)     * Bn * Zd + gi] = zi;
        g.out_z[(size_t)(2 * g.t + 1) * Bn * Zd + gi] = zp;
        __nv_bfloat16 zh, zl; bsplit(zi, zh, zl);
        g.XwHm[(size_t)b * XK + z] = zh;
        g.XwLm[(size_t)b * XK + z] = zl;
    }
}

// ---------------- prep kernels ----------------
__device__ __forceinline__ int perm_n(int np) {
    int chunk = np >> 7, r = np & 127, gate = r >> 5, w = r & 31;
    return gate * 512 + chunk * 32 + w;
}

__global__ void prep_wcat(const float* __restrict__ Wx, const float* __restrict__ Wh) {
    size_t i = (size_t)blockIdx.x * blockDim.x + threadIdx.x;
    if (i >= (size_t)Gd * XK) return;
    int k = (int)(i % XK), np = (int)(i / XK);
    int n = perm_n(np);
    float v;
    if (k < 64)       v = Wx[(size_t)k * Gd + n];
    else if (k < 320) v = Wx[(size_t)(512 + k) * Gd + n];
    else              v = Wh[(size_t)(k - 320) * Gd + n];
    __nv_bfloat16 h, l; bsplit(v, h, l);
    g_WcatT_h[i] = h; g_WcatT_l[i] = l;
}

__global__ void prep_wxh(const float* __restrict__ Wx, const float* __restrict__ bl) {
    size_t i = (size_t)blockIdx.x * blockDim.x + threadIdx.x;
    if (i >= (size_t)Gd * Hd) return;
    int k = (int)(i % Hd), np = (int)(i / Hd);
    int n = perm_n(np);
    __nv_bfloat16 h, l; bsplit(Wx[(size_t)(64 + k) * Gd + n], h, l);
    g_WxhT_h[i] = h; g_WxhT_l[i] = l;
    if (k == 0) g_blstmp[np] = bl[n];
}

__global__ void prep_dec(const float* __restrict__ W1, const float* __restrict__ W2,
                         const float* __restrict__ W3) {
    size_t i = (size_t)blockIdx.x * blockDim.x + threadIdx.x;
    const size_t s1 = Fd * Hd, s2 = s1 + Fd * Fd, s3 = s2 + Fd * Fd;
    __nv_bfloat16 h, l;
    if (i < s1) {
        int k = (int)(i % Hd), n = (int)(i / Hd);
        bsplit(W1[(size_t)k * Fd + n], h, l);
        g_W1T_h[i] = h; g_W1T_l[i] = l;
    } else if (i < s2) {
        size_t j = i - s1; int k = (int)(j % Fd), n = (int)(j / Fd);
        bsplit(W2[(size_t)k * Fd + n], h, l);
        g_W2T_h[j] = h; g_W2T_l[j] = l;
    } else if (i < s3) {
        size_t j = i - s2; int k = (int)(j % Fd), n = (int)(j / Fd);
        bsplit(W3[(size_t)k * Fd + n], h, l);
        g_W3T_h[j] = h; g_W3T_l[j] = l;
    }
}

__global__ void prep_head(const float* __restrict__ W4, const float* __restrict__ W7,
                          const float* __restrict__ b4, const float* __restrict__ b7) {
    size_t i = (size_t)blockIdx.x * blockDim.x + threadIdx.x;
    const size_t s1 = 128 * IK, s2 = s1 + 128 * Hd;
    __nv_bfloat16 h, l;
    if (i < s1) {
        int k = (int)(i % IK), n = (int)(i / IK);
        float v;
        if (n < 64) v = W4[(size_t)(512 + k) * Zd + n];
        else {
            int n2 = n - 64;
            if (k < 512)      v = W7[(size_t)(512 + k) * Zd + n2];
            else if (k < 768) v = 0.f;
            else              v = W7[(size_t)(1024 + k - 768) * Zd + n2];
        }
        bsplit(v, h, l);
        g_WheadT_h[i] = h; g_WheadT_l[i] = l;
    } else if (i < s2) {
        size_t j = i - s1; int k = (int)(j % Hd), n = (int)(j / Hd);
        float v = (n < 64) ? W4[(size_t)k * Zd + n] : W7[(size_t)k * Zd + (n - 64)];
        bsplit(v, h, l);
        g_WbaseT_h[j] = h; g_WbaseT_l[j] = l;
        if (k == 0) g_bhz[n] = (n < 64) ? b4[n] : b7[n - 64];
    }
}

__global__ void prep_hi(const float* __restrict__ h_i) {
    size_t i = (size_t)blockIdx.x * blockDim.x + threadIdx.x;
    if (i >= (size_t)Bn * Hd) return;
    __nv_bfloat16 h, l; bsplit(h_i[i], h, l);
    g_hih[i] = h; g_hil[i] = l;
}

__global__ void zero_state() {
    size_t i = (size_t)blockIdx.x * blockDim.x + threadIdx.x;
    const size_t nx = (size_t)Bn * XK;
    if (i < nx) {
        __nv_bfloat16 z = __float2bfloat16(0.f);
        g_Xh0[i] = z; g_Xl0[i] = z; g_Xh1[i] = z; g_Xl1[i] = z;
        return;
    }
    i -= nx;
    if (i < (size_t)Bn * Hd) g_c[i] = 0.f;
}

// ---------------- host ----------------
template<typename T> static T* sym(const void* s) { void* p = nullptr; cudaGetSymbolAddress(&p, s); return (T*)p; }

extern "C" void kernel_launch(void* const* d_in, const int* in_sizes, int n_in,
                              void* d_out, int out_size) {
    const float* h_i     = (const float*)d_in[0];
    const float* eps_inf = (const float*)d_in[1];
    const float* eps_pri = (const float*)d_in[2];
    const float* Wx      = (const float*)d_in[3];
    const float* Wh      = (const float*)d_in[4];
    const float* b_lstm  = (const float*)d_in[5];
    const float* W1 = (const float*)d_in[6],  *b1 = (const float*)d_in[7];
    const float* W2 = (const float*)d_in[8],  *b2 = (const float*)d_in[9];
    const float* W3 = (const float*)d_in[10], *b3 = (const float*)d_in[11];
    const float* W4 = (const float*)d_in[12], *b4 = (const float*)d_in[13];
    const float* W5 = (const float*)d_in[14], *b5 = (const float*)d_in[15];
    const float* W6 = (const float*)d_in[16], *b6 = (const float*)d_in[17];
    const float* W7 = (const float*)d_in[18], *b7 = (const float*)d_in[19];
    const float* W8 = (const float*)d_in[20], *b8 = (const float*)d_in[21];
    const float* W9 = (const float*)d_in[22], *b9 = (const float*)d_in[23];

    float* out      = (float*)d_out;
    float* out_fake = out;
    float* out_mean = out_fake + (size_t)Bn * Td * Fd;
    float* out_lv   = out_mean + (size_t)Bn * Td * Zd;
    float* out_z    = out_lv   + (size_t)Bn * Td * Zd;

    __nv_bfloat16* Xh0 = sym<__nv_bfloat16>(g_Xh0); __nv_bfloat16* Xl0 = sym<__nv_bfloat16>(g_Xl0);
    __nv_bfloat16* Xh1 = sym<__nv_bfloat16>(g_Xh1); __nv_bfloat16* Xl1 = sym<__nv_bfloat16>(g_Xl1);
    __nv_bfloat16* Ch  = sym<__nv_bfloat16>(g_Ch);  __nv_bfloat16* Cl  = sym<__nv_bfloat16>(g_Cl);

    float* pBaseg  = sym<float>(g_baseg);
    float* pBasehz = sym<float>(g_basehz);
    float* pBlstmp = sym<float>(g_blstmp);
    float* pBhz    = sym<float>(g_bhz);

    constexpr int SM128128 = (128 + 128) * 160 * 2;   // 81920
    constexpr int SM6464   = (64 + 64) * 160 * 2;     // 40960
    constexpr int SMTAIL   = 174080;
    cudaFuncSetAttribute(gemm<128,128,64,32,256,0,1>, cudaFuncAttributeMaxDynamicSharedMemorySize, SM128128);
    cudaFuncSetAttribute(gemm<128,128,64,32,256,1,2>, cudaFuncAttributeMaxDynamicSharedMemorySize, SM128128);
    cudaFuncSetAttribute(gemm<64,64,32,32,128,0,1>,   cudaFuncAttributeMaxDynamicSharedMemorySize, SM6464);
    cudaFuncSetAttribute(tail_kernel,                 cudaFuncAttributeMaxDynamicSharedMemorySize, SMTAIL);

    // ---- init ----
    {
        size_t n = (size_t)Bn * XK + (size_t)Bn * Hd;
        zero_state<<<(unsigned)((n + 255) / 256), 256>>>();
        prep_wcat<<<(unsigned)(((size_t)Gd * XK + 255) / 256), 256>>>(Wx, Wh);
        prep_wxh<<<(unsigned)(((size_t)Gd * Hd + 255) / 256), 256>>>(Wx, b_lstm);
        prep_dec<<<(unsigned)(((size_t)Fd * Hd + 2 * Fd * Fd + 255) / 256), 256>>>(W1, W2, W3);
        prep_head<<<(unsigned)((128 * (IK + Hd) + 255) / 256), 256>>>(W4, W7, b4, b7);
        prep_hi<<<(unsigned)(((size_t)Bn * Hd + 255) / 256), 256>>>(h_i);
    }

    // ---- hoisted base GEMMs ----
    {
        GArgs b{};
        b.Ah = sym<__nv_bfloat16>(g_hih); b.Al = sym<__nv_bfloat16>(g_hil); b.lda = Hd;
        b.Bh = sym<__nv_bfloat16>(g_WxhT_h); b.Bl = sym<__nv_bfloat16>(g_WxhT_l); b.ldb = Hd;
        b.Ci = pBlstmp; b.C = pBaseg; b.ldc = Gd; b.K = Hd;
        gemm<128,128,64,32,256,0,1><<<dim3(16, 32), 256, SM128128>>>(b);

        b.Bh = sym<__nv_bfloat16>(g_WbaseT_h); b.Bl = sym<__nv_bfloat16>(g_WbaseT_l); b.ldb = Hd;
        b.Ci = pBhz; b.C = pBasehz; b.ldc = 128; b.K = Hd;
        gemm<64,64,32,32,128,0,1><<<dim3(2, 64), 128, SM6464>>>(b);
    }

    for (int t = 0; t < Td; t++) {
        __nv_bfloat16* XrH = (t & 1) ? Xh1 : Xh0;
        __nv_bfloat16* XrL = (t & 1) ? Xl1 : Xl0;
        __nv_bfloat16* XwH = (t & 1) ? Xh0 : Xh1;
        __nv_bfloat16* XwL = (t & 1) ? Xl0 : Xl1;

        // gate GEMM + fused LSTM (reads Xr; writes h->Xw, c->Ch/Cl)
        {
            GArgs b{};
            b.Ah = XrH; b.Al = XrL; b.lda = XK;
            b.Bh = sym<__nv_bfloat16>(g_WcatT_h); b.Bl = sym<__nv_bfloat16>(g_WcatT_l); b.ldb = XK;
            b.Ci = pBaseg; b.ldci = Gd; b.K = XK;
            b.cst = sym<float>(g_c);
            b.Xh = XwH; b.Xl = XwL;
            b.Ch = Ch; b.Cl = Cl;
            gemm<128,128,64,32,256,1,2><<<dim3(16, 32), 256, SM128128>>>(b);
        }
        // fused tail
        {
            TailArgs ta{};
            ta.XwH = XwH; ta.XwL = XwL; ta.XwHm = XwH; ta.XwLm = XwL;
            ta.XrH = XrH; ta.XrL = XrL;
            ta.Ch = Ch; ta.Cl = Cl;
            ta.basehz = pBasehz;
            ta.b1 = b1; ta.b2 = b2; ta.b3 = b3;
            ta.W5 = W5; ta.b5 = b5; ta.W6 = W6; ta.b6 = b6;
            ta.W8 = W8; ta.b8 = b8; ta.W9 = W9; ta.b9 = b9;
            ta.eps_inf = eps_inf; ta.eps_pri = eps_pri;
            ta.fake = out_fake; ta.out_mean = out_mean; ta.out_lv = out_lv; ta.out_z = out_z;
            ta.t = t;
            tail_kernel<<<Bn / 32, 128, SMTAIL>>>(ta);
        }
    }
}

// round 7
// speedup vs baseline: 1.0973x; 1.0276x over previous
#include <cuda_runtime.h>
#include <cuda_bf16.h>
#include <math.h>
#include <stdint.h>

#define Bn   4096
#define Hd   512
#define Fd   256
#define Zd   64
#define Td   16
#define Gd   2048
#define XK   832      // bf16 X row: [z(64) | y(256) | h(512)]
#define IK   1024     // head K:     [c(512) | y_j(256) | y_prev(256)]
#define CK   512      // c buffer row

// ---------------- persistent buffers ----------------
__device__ float g_baseg [(size_t)Bn * Gd];    // permuted layout
__device__ float g_basehz[Bn * 128];           // [base4 | base7]
__device__ float g_c     [Bn * Hd];
__device__ float g_blstmp[Gd];
__device__ float g_bhz   [128];

// double-buffered state X
__device__ __nv_bfloat16 g_Xh0[(size_t)Bn * XK], g_Xl0[(size_t)Bn * XK];
__device__ __nv_bfloat16 g_Xh1[(size_t)Bn * XK], g_Xl1[(size_t)Bn * XK];
__device__ __nv_bfloat16 g_Ch [(size_t)Bn * CK], g_Cl [(size_t)Bn * CK];
__device__ __nv_bfloat16 g_hih[(size_t)Bn * Hd], g_hil[(size_t)Bn * Hd];

// weights: n-major [N][K] bf16 hi/lo
__device__ __nv_bfloat16 g_WcatT_h[(size_t)Gd * XK], g_WcatT_l[(size_t)Gd * XK];
__device__ __nv_bfloat16 g_WxhT_h [(size_t)Gd * Hd], g_WxhT_l [(size_t)Gd * Hd];
__device__ __nv_bfloat16 g_W1T_h  [Fd * Hd], g_W1T_l  [Fd * Hd];
__device__ __nv_bfloat16 g_W2T_h  [Fd * Fd], g_W2T_l  [Fd * Fd];
__device__ __nv_bfloat16 g_W3T_h  [Fd * Fd], g_W3T_l  [Fd * Fd];
__device__ __nv_bfloat16 g_WheadT_h[128 * IK], g_WheadT_l[128 * IK];
__device__ __nv_bfloat16 g_WbaseT_h[128 * Hd], g_WbaseT_l[128 * Hd];

// ---------------- helpers ----------------
__device__ __forceinline__ void bsplit(float v, __nv_bfloat16& h, __nv_bfloat16& l) {
    h = __float2bfloat16_rn(v);
    l = __float2bfloat16_rn(v - __bfloat162float(h));
}
__device__ __forceinline__ uint32_t bpack(__nv_bfloat16 a, __nv_bfloat16 b) {
    __nv_bfloat162 t; t.x = a; t.y = b;
    return reinterpret_cast<uint32_t&>(t);
}
__device__ __forceinline__ __nv_bfloat162 bmk2(__nv_bfloat16 a, __nv_bfloat16 b) {
    __nv_bfloat162 t; t.x = a; t.y = b; return t;
}
__device__ __forceinline__ void mma16816(float* c, const uint32_t* a, const uint32_t* b) {
    asm volatile(
        "mma.sync.aligned.m16n8k16.row.col.f32.bf16.bf16.f32 "
        "{%0,%1,%2,%3}, {%4,%5,%6,%7}, {%8,%9}, {%0,%1,%2,%3};\n"
        : "+f"(c[0]), "+f"(c[1]), "+f"(c[2]), "+f"(c[3])
        : "r"(a[0]), "r"(a[1]), "r"(a[2]), "r"(a[3]), "r"(b[0]), "r"(b[1]));
}
__device__ __forceinline__ void cpa16(void* dst, const void* src) {
    uint32_t d = (uint32_t)__cvta_generic_to_shared(dst);
    asm volatile("cp.async.cg.shared.global [%0], [%1], 16;\n" :: "r"(d), "l"(src));
}
#define CPA_COMMIT() asm volatile("cp.async.commit_group;\n")
#define CPA_WAIT1()  asm volatile("cp.async.wait_group 1;\n")
#define CPA_WAIT0()  asm volatile("cp.async.wait_group 0;\n")

template<int MT,int NTL,int AHS,int BHS>
__device__ __forceinline__ void stage_mma2(const char* Ab, const char* Bb, float* acc,
                                           int wm, int wn, int gq, int tg)
{
    const uint32_t* As_h = (const uint32_t*)Ab;
    const uint32_t* As_l = (const uint32_t*)(Ab + AHS);
    const uint32_t* Bs_h = (const uint32_t*)Bb;
    const uint32_t* Bs_l = (const uint32_t*)(Bb + BHS);
#pragma unroll
    for (int kk = 0; kk < 16; kk += 8) {
        uint32_t ah[MT][4], al[MT][4], bh[NTL][2], bl[NTL][2];
#pragma unroll
        for (int mt = 0; mt < MT; mt++) {
            int r = wm + mt * 16 + gq;
            ah[mt][0] = As_h[r * 20 + kk + tg];
            ah[mt][1] = As_h[(r + 8) * 20 + kk + tg];
            ah[mt][2] = As_h[r * 20 + kk + tg + 4];
            ah[mt][3] = As_h[(r + 8) * 20 + kk + tg + 4];
            al[mt][0] = As_l[r * 20 + kk + tg];
            al[mt][1] = As_l[(r + 8) * 20 + kk + tg];
            al[mt][2] = As_l[r * 20 + kk + tg + 4];
            al[mt][3] = As_l[(r + 8) * 20 + kk + tg + 4];
        }
#pragma unroll
        for (int nt = 0; nt < NTL; nt++) {
            int r = wn + nt * 8 + gq;
            bh[nt][0] = Bs_h[r * 20 + kk + tg];
            bh[nt][1] = Bs_h[r * 20 + kk + tg + 4];
            bl[nt][0] = Bs_l[r * 20 + kk + tg];
            bl[nt][1] = Bs_l[r * 20 + kk + tg + 4];
        }
#pragma unroll
        for (int mt = 0; mt < MT; mt++)
#pragma unroll
            for (int nt = 0; nt < NTL; nt++) {
                float* a = acc + (mt * NTL + nt) * 4;
                mma16816(a, ah[mt], bh[nt]);
                mma16816(a, ah[mt], bl[nt]);
                mma16816(a, al[mt], bh[nt]);
            }
    }
}

// ================= gate GEMM (+fused LSTM) =================
struct GArgs {
    const __nv_bfloat16 *Ah, *Al; int lda;
    const __nv_bfloat16 *Bh, *Bl; int ldb;
    const float* Ci; int ldci;
    float* C; int ldc;
    int K;
    float* cst;
    __nv_bfloat16 *Xh, *Xl;
    __nv_bfloat16 *Ch, *Cl;
};

template<int BM,int BN,int NTH>
__device__ __forceinline__ void stage_load(char* base, int tid, int bm, int bn,
    const __nv_bfloat16* Ah, const __nv_bfloat16* Al, int lda,
    const __nv_bfloat16* Bh, const __nv_bfloat16* Bl, int ldb, int k0)
{
#pragma unroll
    for (int i = tid; i < BM * 4; i += NTH) {
        int row = i >> 2, c4 = (i & 3) * 16;
        size_t off = ((size_t)(bm + row) * lda + k0) * 2 + c4;
        cpa16(base + row * 80 + c4, (const char*)Ah + off);
        cpa16(base + BM * 80 + row * 80 + c4, (const char*)Al + off);
    }
#pragma unroll
    for (int i = tid; i < BN * 4; i += NTH) {
        int row = i >> 2, c4 = (i & 3) * 16;
        size_t off = ((size_t)(bn + row) * ldb + k0) * 2 + c4;
        cpa16(base + BM * 160 + row * 80 + c4, (const char*)Bh + off);
        cpa16(base + BM * 160 + BN * 80 + row * 80 + c4, (const char*)Bl + off);
    }
    CPA_COMMIT();
}

template<int BM,int BN,int WM,int WN,int NTH,int EPI,int CI>
__global__ void __launch_bounds__(NTH) gemm(GArgs g)
{
    extern __shared__ char sm[];
    constexpr int MT = WM / 16, NTL = WN / 8, NWN = BN / WN;
    constexpr int stageB = (BM + BN) * 160;
    const int tid = threadIdx.x, warp = tid >> 5, lane = tid & 31;
    const int gq = lane >> 2, tg = lane & 3;
    const int wm = (warp / NWN) * WM, wn = (warp % NWN) * WN;
    const int bm = blockIdx.y * BM, bn = blockIdx.x * BN;
    const int K = g.K;

    float acc[MT * NTL * 4];
#pragma unroll
    for (int i = 0; i < MT * NTL * 4; i++) acc[i] = 0.f;

    const int nk = K >> 5;
    stage_load<BM,BN,NTH>(sm, tid, bm, bn, g.Ah, g.Al, g.lda, g.Bh, g.Bl, g.ldb, 0);
    for (int kt = 0; kt < nk; kt++) {
        if (kt + 1 < nk) {
            stage_load<BM,BN,NTH>(sm + ((kt + 1) & 1) * stageB, tid, bm, bn,
                                  g.Ah, g.Al, g.lda, g.Bh, g.Bl, g.ldb, (kt + 1) << 5);
            CPA_WAIT1();
        } else {
            CPA_WAIT0();
        }
        __syncthreads();
        const char* cur = sm + (kt & 1) * stageB;
        stage_mma2<MT,NTL,BM*80,BN*80>(cur, cur + BM * 160, acc, wm, wn, gq, tg);
        __syncthreads();
    }

    if (EPI == 1) {
        float* tile = (float*)sm;
#pragma unroll
        for (int mt = 0; mt < MT; mt++)
#pragma unroll
            for (int nt = 0; nt < NTL; nt++) {
                int r0 = wm + mt * 16 + gq, c0 = wn + nt * 8 + 2 * tg;
                float* a = acc + (mt * NTL + nt) * 4;
                const float* ci0 = g.Ci + (size_t)(bm + r0) * g.ldci + bn + c0;
                const float* ci1 = g.Ci + (size_t)(bm + r0 + 8) * g.ldci + bn + c0;
                tile[r0 * BN + c0]           = a[0] + ci0[0];
                tile[r0 * BN + c0 + 1]       = a[1] + ci0[1];
                tile[(r0 + 8) * BN + c0]     = a[2] + ci1[0];
                tile[(r0 + 8) * BN + c0 + 1] = a[3] + ci1[1];
            }
        __syncthreads();
        for (int idx = tid; idx < BM * 32; idx += NTH) {
            int row = idx >> 5, w = idx & 31;
            float ig = tile[row * BN + w];
            float fg = tile[row * BN + 32 + w];
            float gg = tile[row * BN + 64 + w];
            float og = tile[row * BN + 96 + w];
            int b = bm + row, j = blockIdx.x * 32 + w;
            float si = 1.f / (1.f + expf(-ig));
            float sf = 1.f / (1.f + expf(-fg));
            float so = 1.f / (1.f + expf(-og));
            float cn = sf * g.cst[b * Hd + j] + si * tanhf(gg);
            float hn = so * tanhf(cn);
            g.cst[b * Hd + j] = cn;
            __nv_bfloat16 hh, hl, ch, cl;
            bsplit(hn, hh, hl); bsplit(cn, ch, cl);
            g.Xh[(size_t)b * XK + 320 + j] = hh;
            g.Xl[(size_t)b * XK + 320 + j] = hl;
            g.Ch[(size_t)b * CK + j] = ch;
            g.Cl[(size_t)b * CK + j] = cl;
        }
        return;
    }

#pragma unroll
    for (int mt = 0; mt < MT; mt++)
#pragma unroll
        for (int nt = 0; nt < NTL; nt++) {
            float* a = acc + (mt * NTL + nt) * 4;
#pragma unroll
            for (int half = 0; half < 2; half++) {
                int r = bm + wm + mt * 16 + gq + half * 8;
                int c = bn + wn + nt * 8 + 2 * tg;
                float v0 = a[half * 2], v1 = a[half * 2 + 1];
                if (CI == 1) { v0 += g.Ci[c]; v1 += g.Ci[c + 1]; }
                *(float2*)&g.C[(size_t)r * g.ldc + c] = make_float2(v0, v1);
            }
        }
}

// ================= fused tail kernel (256 threads / 8 warps) =================
struct TailArgs {
    const __nv_bfloat16 *XwH, *XwL;
    __nv_bfloat16 *XwHm, *XwLm;
    const __nv_bfloat16 *XrH, *XrL;
    const __nv_bfloat16 *Ch, *Cl;
    const float* basehz;
    const float *b1, *b2, *b3;
    const float *W5, *b5, *W6, *b6, *W8, *b8, *W9, *b9;
    const float *eps_inf, *eps_pri;
    float *fake, *out_mean, *out_lv, *out_z;
    int t;
};

template<int BN,int NTH>
__device__ __forceinline__ void tail_loadB(char* st, int tid,
    const __nv_bfloat16* Bh, const __nv_bfloat16* Bl, int ldb, int kg)
{
#pragma unroll
    for (int i = tid; i < BN * 4; i += NTH) {
        int row = i >> 2, c4 = (i & 3) * 16;
        size_t off = ((size_t)row * ldb + kg) * 2 + c4;
        cpa16(st + row * 80 + c4, (const char*)Bh + off);
        cpa16(st + BN * 80 + row * 80 + c4, (const char*)Bl + off);
    }
}

__device__ __forceinline__ void tail_loadA(char* st, int tid, int r0,
    const __nv_bfloat16* Ah, const __nv_bfloat16* Al, int lda, int kg)
{
    if (tid >= 128) return;
    int arow = tid >> 2, ac4 = (tid & 3) * 16;
    size_t off = ((size_t)(r0 + arow) * lda + kg) * 2 + ac4;
    cpa16(st + arow * 80 + ac4, (const char*)Ah + off);
    cpa16(st + 2560 + arow * 80 + ac4, (const char*)Al + off);
}

// write relu(acc+bias) -> chunked bf16 hi/lo A-layout (chunk stride 5120, lo at +2560)
template<int NTL>
__device__ __forceinline__ void epi_chunk(const float* acc, const float* bias,
                                          char* dst, int wn, int gq, int tg)
{
#pragma unroll
    for (int mt = 0; mt < 2; mt++)
#pragma unroll
        for (int nt = 0; nt < NTL; nt++)
#pragma unroll
            for (int half = 0; half < 2; half++) {
                int row = mt * 16 + gq + half * 8;
                int col = wn + nt * 8 + 2 * tg;
                const float* a = acc + (mt * NTL + nt) * 4 + half * 2;
                float v0 = fmaxf(a[0] + bias[col], 0.f);
                float v1 = fmaxf(a[1] + bias[col + 1], 0.f);
                __nv_bfloat16 h0, l0, h1, l1;
                bsplit(v0, h0, l0); bsplit(v1, h1, l1);
                char* cb = dst + (col >> 5) * 5120;
                int kp = (col & 31) >> 1;
                ((uint32_t*)cb)[row * 20 + kp] = bpack(h0, h1);
                ((uint32_t*)(cb + 2560))[row * 20 + kp] = bpack(l0, l1);
            }
}

__global__ void __launch_bounds__(256) tail_kernel(TailArgs g)
{
    extern __shared__ char sm[];
    char* stages = sm;
    char* tA = sm + 92160;
    char* tB = sm + 133120;
    float* hzc = (float*)tB;

    const int tid = threadIdx.x, lane = tid & 31, warp = tid >> 5;
    const int gq = lane >> 2, tg = lane & 3;
    const int r0 = blockIdx.x * 32;
    constexpr int DST = 46080;
    constexpr int HST = 25600;

    // ---------- dec1: t1 = relu(h @ W1 + b1)  K=512, BN=256 ----------
    {
        float acc[32];
#pragma unroll
        for (int i = 0; i < 32; i++) acc[i] = 0.f;
        tail_loadA(stages, tid, r0, g.XwH + 320, g.XwL + 320, XK, 0);
        tail_loadB<256,256>(stages + 5120, tid, g_W1T_h, g_W1T_l, Hd, 0);
        CPA_COMMIT();
        for (int kt = 0; kt < 16; kt++) {
            char* cur = stages + (kt & 1) * DST;
            if (kt < 15) {
                char* nxt = stages + ((kt + 1) & 1) * DST;
                tail_loadA(nxt, tid, r0, g.XwH + 320, g.XwL + 320, XK, (kt + 1) * 32);
                tail_loadB<256,256>(nxt + 5120, tid, g_W1T_h, g_W1T_l, Hd, (kt + 1) * 32);
                CPA_COMMIT(); CPA_WAIT1();
            } else CPA_WAIT0();
            __syncthreads();
            stage_mma2<2,4,2560,20480>(cur, cur + 5120, acc, 0, warp * 32, gq, tg);
            __syncthreads();
        }
        epi_chunk<4>(acc, g.b1, tA, warp * 32, gq, tg);
        __syncthreads();
    }
    // ---------- dec2: t2 = relu(t1 @ W2 + b2)  K=256 local ----------
    {
        float acc[32];
#pragma unroll
        for (int i = 0; i < 32; i++) acc[i] = 0.f;
        tail_loadB<256,256>(stages + 5120, tid, g_W2T_h, g_W2T_l, Fd, 0);
        CPA_COMMIT();
        for (int kt = 0; kt < 8; kt++) {
            char* cur = stages + (kt & 1) * DST;
            if (kt < 7) {
                tail_loadB<256,256>(stages + ((kt + 1) & 1) * DST + 5120, tid,
                                    g_W2T_h, g_W2T_l, Fd, (kt + 1) * 32);
                CPA_COMMIT(); CPA_WAIT1();
            } else CPA_WAIT0();
            __syncthreads();
            stage_mma2<2,4,2560,20480>(tA + kt * 5120, cur + 5120, acc, 0, warp * 32, gq, tg);
            __syncthreads();
        }
        epi_chunk<4>(acc, g.b2, tB, warp * 32, gq, tg);
        __syncthreads();
    }
    // ---------- dec3: y = relu(t2 @ W3 + b3) -> fake, Xw y, yj(local) ----------
    {
        float acc[32];
#pragma unroll
        for (int i = 0; i < 32; i++) acc[i] = 0.f;
        tail_loadB<256,256>(stages + 5120, tid, g_W3T_h, g_W3T_l, Fd, 0);
        CPA_COMMIT();
        for (int kt = 0; kt < 8; kt++) {
            char* cur = stages + (kt & 1) * DST;
            if (kt < 7) {
                tail_loadB<256,256>(stages + ((kt + 1) & 1) * DST + 5120, tid,
                                    g_W3T_h, g_W3T_l, Fd, (kt + 1) * 32);
                CPA_COMMIT(); CPA_WAIT1();
            } else CPA_WAIT0();
            __syncthreads();
            stage_mma2<2,4,2560,20480>(tB + kt * 5120, cur + 5120, acc, 0, warp * 32, gq, tg);
            __syncthreads();
        }
#pragma unroll
        for (int mt = 0; mt < 2; mt++)
#pragma unroll
            for (int nt = 0; nt < 4; nt++)
#pragma unroll
                for (int half = 0; half < 2; half++) {
                    int row = mt * 16 + gq + half * 8;
                    int col = warp * 32 + nt * 8 + 2 * tg;
                    int b = r0 + row;
                    const float* a = acc + (mt * 4 + nt) * 4 + half * 2;
                    float v0 = fmaxf(a[0] + g.b3[col], 0.f);
                    float v1 = fmaxf(a[1] + g.b3[col + 1], 0.f);
                    *(float2*)&g.fake[(size_t)b * (Td * Fd) + g.t * Fd + col] = make_float2(v0, v1);
                    __nv_bfloat16 h0, l0, h1, l1;
                    bsplit(v0, h0, l0); bsplit(v1, h1, l1);
                    *(__nv_bfloat162*)&g.XwHm[(size_t)b * XK + 64 + col] = bmk2(h0, h1);
                    *(__nv_bfloat162*)&g.XwLm[(size_t)b * XK + 64 + col] = bmk2(l0, l1);
                    char* cb = tA + (col >> 5) * 5120;
                    int kp = (col & 31) >> 1;
                    ((uint32_t*)cb)[row * 20 + kp] = bpack(h0, h1);
                    ((uint32_t*)(cb + 2560))[row * 20 + kp] = bpack(l0, l1);
                }
        __syncthreads();
    }
    // ---------- head: [hz|hzp] = relu(I @ Whead + basehz)  K=1024, BN=128 ----------
    {
        float acc[16];
#pragma unroll
        for (int i = 0; i < 16; i++) acc[i] = 0.f;
        tail_loadA(stages, tid, r0, g.Ch, g.Cl, CK, 0);
        tail_loadB<128,256>(stages + 5120, tid, g_WheadT_h, g_WheadT_l, IK, 0);
        CPA_COMMIT();
        for (int kt = 0; kt < 32; kt++) {
            char* cur = stages + (kt & 1) * HST;
            if (kt < 31) {
                char* nxt = stages + ((kt + 1) & 1) * HST;
                int kn = kt + 1;
                if (kn < 16)       tail_loadA(nxt, tid, r0, g.Ch, g.Cl, CK, kn * 32);
                else if (kn >= 24) tail_loadA(nxt, tid, r0, g.XrH, g.XrL, XK, 64 + (kn - 24) * 32);
                tail_loadB<128,256>(nxt + 5120, tid, g_WheadT_h, g_WheadT_l, IK, kn * 32);
                CPA_COMMIT(); CPA_WAIT1();
            } else CPA_WAIT0();
            __syncthreads();
            const char* Ab = (kt >= 16 && kt < 24) ? (tA + (kt - 16) * 5120) : cur;
            stage_mma2<2,2,2560,10240>(Ab, cur + 5120, acc, 0, warp * 16, gq, tg);
            __syncthreads();
        }
#pragma unroll
        for (int mt = 0; mt < 2; mt++)
#pragma unroll
            for (int nt = 0; nt < 2; nt++)
#pragma unroll
                for (int half = 0; half < 2; half++) {
                    int row = mt * 16 + gq + half * 8;
                    int col = warp * 16 + nt * 8 + 2 * tg;
                    const float* a = acc + (mt * 2 + nt) * 4 + half * 2;
                    const float* bz = g.basehz + (size_t)(r0 + row) * 128 + col;
                    hzc[row * 130 + col]     = fmaxf(a[0] + bz[0], 0.f);
                    hzc[row * 130 + col + 1] = fmaxf(a[1] + bz[1], 0.f);
                }
        __syncthreads();
    }
    // ---------- finish ----------
    for (int idx = tid; idx < 32 * 64; idx += 256) {
        int row = idx >> 6, z = idx & 63, b = r0 + row;
        float m = g.b5[z], l = g.b6[z], mp = g.b8[z], lp = g.b9[z];
        const float* hz = &hzc[row * 130];
#pragma unroll 8
        for (int k = 0; k < 64; k++) {
            float av = hz[k], ap = hz[64 + k];
            m  += av * g.W5[k * Zd + z];
            l  += av * g.W6[k * Zd + z];
            mp += ap * g.W8[k * Zd + z];
            lp += ap * g.W9[k * Zd + z];
        }
        m = fmaxf(m, 0.f); l = fmaxf(l, 0.f); mp = fmaxf(mp, 0.f); lp = fmaxf(lp, 0.f);
        size_t gi = (size_t)b * Zd + z;
        float zi = m  + g.eps_inf[(size_t)g.t * Bn * Zd + gi] * sqrtf(expf(l));
        float zp = mp + g.eps_pri[(size_t)g.t * Bn * Zd + gi] * sqrtf(expf(lp));
        g.out_mean[(size_t)b * Td * Zd + (size_t)g.t * Zd + z] = m;
        g.out_lv  [(size_t)b * Td * Zd + (size_t)g.t * Zd + z] = l;
        g.out_z[(size_t)(2 * g.t)     * Bn * Zd + gi] = zi;
        g.out_z[(size_t)(2 * g.t + 1) * Bn * Zd + gi] = zp;
        __nv_bfloat16 zh, zl; bsplit(zi, zh, zl);
        g.XwHm[(size_t)b * XK + z] = zh;
        g.XwLm[(size_t)b * XK + z] = zl;
    }
}

// ---------------- single merged prep kernel ----------------
__device__ __forceinline__ int perm_n(int np) {
    int chunk = np >> 7, r = np & 127, gate = r >> 5, w = r & 31;
    return gate * 512 + chunk * 32 + w;
}

__global__ void prep_all(const float* __restrict__ h_i,
                         const float* __restrict__ Wx, const float* __restrict__ Wh,
                         const float* __restrict__ bl,
                         const float* __restrict__ W1, const float* __restrict__ W2,
                         const float* __restrict__ W3,
                         const float* __restrict__ W4, const float* __restrict__ W7,
                         const float* __restrict__ b4, const float* __restrict__ b7)
{
    size_t i = (size_t)blockIdx.x * blockDim.x + threadIdx.x;
    __nv_bfloat16 h, l;

    // 1) zero X buffers + c
    const size_t nX = (size_t)Bn * XK;
    if (i < nX) {
        __nv_bfloat16 z = __float2bfloat16(0.f);
        g_Xh0[i] = z; g_Xl0[i] = z; g_Xh1[i] = z; g_Xl1[i] = z;
        return;
    }
    i -= nX;
    const size_t nC = (size_t)Bn * Hd;
    if (i < nC) { g_c[i] = 0.f; return; }
    i -= nC;
    // 2) h_i split
    if (i < (size_t)Bn * Hd) {
        bsplit(h_i[i], h, l);
        g_hih[i] = h; g_hil[i] = l;
        return;
    }
    i -= (size_t)Bn * Hd;
    // 3) Wcat
    if (i < (size_t)Gd * XK) {
        int k = (int)(i % XK), np = (int)(i / XK);
        int n = perm_n(np);
        float v;
        if (k < 64)       v = Wx[(size_t)k * Gd + n];
        else if (k < 320) v = Wx[(size_t)(512 + k) * Gd + n];
        else              v = Wh[(size_t)(k - 320) * Gd + n];
        bsplit(v, h, l);
        g_WcatT_h[i] = h; g_WcatT_l[i] = l;
        return;
    }
    i -= (size_t)Gd * XK;
    // 4) Wxh
    if (i < (size_t)Gd * Hd) {
        int k = (int)(i % Hd), np = (int)(i / Hd);
        int n = perm_n(np);
        bsplit(Wx[(size_t)(64 + k) * Gd + n], h, l);
        g_WxhT_h[i] = h; g_WxhT_l[i] = l;
        if (k == 0) g_blstmp[np] = bl[n];
        return;
    }
    i -= (size_t)Gd * Hd;
    // 5) decoder weights
    if (i < (size_t)Fd * Hd) {
        int k = (int)(i % Hd), n = (int)(i / Hd);
        bsplit(W1[(size_t)k * Fd + n], h, l);
        g_W1T_h[i] = h; g_W1T_l[i] = l;
        return;
    }
    i -= (size_t)Fd * Hd;
    if (i < (size_t)Fd * Fd) {
        int k = (int)(i % Fd), n = (int)(i / Fd);
        bsplit(W2[(size_t)k * Fd + n], h, l);
        g_W2T_h[i] = h; g_W2T_l[i] = l;
        return;
    }
    i -= (size_t)Fd * Fd;
    if (i < (size_t)Fd * Fd) {
        int k = (int)(i % Fd), n = (int)(i / Fd);
        bsplit(W3[(size_t)k * Fd + n], h, l);
        g_W3T_h[i] = h; g_W3T_l[i] = l;
        return;
    }
    i -= (size_t)Fd * Fd;
    // 6) head weights
    if (i < (size_t)128 * IK) {
        int k = (int)(i % IK), n = (int)(i / IK);
        float v;
        if (n < 64) v = W4[(size_t)(512 + k) * Zd + n];
        else {
            int n2 = n - 64;
            if (k < 512)      v = W7[(size_t)(512 + k) * Zd + n2];
            else if (k < 768) v = 0.f;
            else              v = W7[(size_t)(1024 + k - 768) * Zd + n2];
        }
        bsplit(v, h, l);
        g_WheadT_h[i] = h; g_WheadT_l[i] = l;
        return;
    }
    i -= (size_t)128 * IK;
    if (i < (size_t)128 * Hd) {
        int k = (int)(i % Hd), n = (int)(i / Hd);
        float v = (n < 64) ? W4[(size_t)k * Zd + n] : W7[(size_t)k * Zd + (n - 64)];
        bsplit(v, h, l);
        g_WbaseT_h[i] = h; g_WbaseT_l[i] = l;
        if (k == 0) g_bhz[n] = (n < 64) ? b4[n] : b7[n - 64];
    }
}

// ---------------- host ----------------
template<typename T> static T* sym(const void* s) { void* p = nullptr; cudaGetSymbolAddress(&p, s); return (T*)p; }

extern "C" void kernel_launch(void* const* d_in, const int* in_sizes, int n_in,
                              void* d_out, int out_size) {
    const float* h_i     = (const float*)d_in[0];
    const float* eps_inf = (const float*)d_in[1];
    const float* eps_pri = (const float*)d_in[2];
    const float* Wx      = (const float*)d_in[3];
    const float* Wh      = (const float*)d_in[4];
    const float* b_lstm  = (const float*)d_in[5];
    const float* W1 = (const float*)d_in[6],  *b1 = (const float*)d_in[7];
    const float* W2 = (const float*)d_in[8],  *b2 = (const float*)d_in[9];
    const float* W3 = (const float*)d_in[10], *b3 = (const float*)d_in[11];
    const float* W4 = (const float*)d_in[12], *b4 = (const float*)d_in[13];
    const float* W5 = (const float*)d_in[14], *b5 = (const float*)d_in[15];
    const float* W6 = (const float*)d_in[16], *b6 = (const float*)d_in[17];
    const float* W7 = (const float*)d_in[18], *b7 = (const float*)d_in[19];
    const float* W8 = (const float*)d_in[20], *b8 = (const float*)d_in[21];
    const float* W9 = (const float*)d_in[22], *b9 = (const float*)d_in[23];

    float* out      = (float*)d_out;
    float* out_fake = out;
    float* out_mean = out_fake + (size_t)Bn * Td * Fd;
    float* out_lv   = out_mean + (size_t)Bn * Td * Zd;
    float* out_z    = out_lv   + (size_t)Bn * Td * Zd;

    __nv_bfloat16* Xh0 = sym<__nv_bfloat16>(g_Xh0); __nv_bfloat16* Xl0 = sym<__nv_bfloat16>(g_Xl0);
    __nv_bfloat16* Xh1 = sym<__nv_bfloat16>(g_Xh1); __nv_bfloat16* Xl1 = sym<__nv_bfloat16>(g_Xl1);
    __nv_bfloat16* Ch  = sym<__nv_bfloat16>(g_Ch);  __nv_bfloat16* Cl  = sym<__nv_bfloat16>(g_Cl);

    float* pBaseg  = sym<float>(g_baseg);
    float* pBasehz = sym<float>(g_basehz);
    float* pBlstmp = sym<float>(g_blstmp);
    float* pBhz    = sym<float>(g_bhz);

    constexpr int SM128128 = (128 + 128) * 160 * 2;   // 81920
    constexpr int SM6464   = (64 + 64) * 160 * 2;     // 40960
    constexpr int SMTAIL   = 174080;
    cudaFuncSetAttribute(gemm<128,128,64,32,256,0,1>, cudaFuncAttributeMaxDynamicSharedMemorySize, SM128128);
    cudaFuncSetAttribute(gemm<128,128,64,32,256,1,2>, cudaFuncAttributeMaxDynamicSharedMemorySize, SM128128);
    cudaFuncSetAttribute(gemm<64,64,32,32,128,0,1>,   cudaFuncAttributeMaxDynamicSharedMemorySize, SM6464);
    cudaFuncSetAttribute(tail_kernel,                 cudaFuncAttributeMaxDynamicSharedMemorySize, SMTAIL);

    // ---- init (single launch) ----
    {
        size_t tot = (size_t)Bn * XK + 2 * (size_t)Bn * Hd
                   + (size_t)Gd * XK + (size_t)Gd * Hd
                   + (size_t)Fd * Hd + 2 * (size_t)Fd * Fd
                   + (size_t)128 * IK + (size_t)128 * Hd;
        prep_all<<<(unsigned)((tot + 255) / 256), 256>>>(h_i, Wx, Wh, b_lstm,
                                                         W1, W2, W3, W4, W7, b4, b7);
    }

    // ---- hoisted base GEMMs ----
    {
        GArgs b{};
        b.Ah = sym<__nv_bfloat16>(g_hih); b.Al = sym<__nv_bfloat16>(g_hil); b.lda = Hd;
        b.Bh = sym<__nv_bfloat16>(g_WxhT_h); b.Bl = sym<__nv_bfloat16>(g_WxhT_l); b.ldb = Hd;
        b.Ci = pBlstmp; b.C = pBaseg; b.ldc = Gd; b.K = Hd;
        gemm<128,128,64,32,256,0,1><<<dim3(16, 32), 256, SM128128>>>(b);

        b.Bh = sym<__nv_bfloat16>(g_WbaseT_h); b.Bl = sym<__nv_bfloat16>(g_WbaseT_l); b.ldb = Hd;
        b.Ci = pBhz; b.C = pBasehz; b.ldc = 128; b.K = Hd;
        gemm<64,64,32,32,128,0,1><<<dim3(2, 64), 128, SM6464>>>(b);
    }

    for (int t = 0; t < Td; t++) {
        __nv_bfloat16* XrH = (t & 1) ? Xh1 : Xh0;
        __nv_bfloat16* XrL = (t & 1) ? Xl1 : Xl0;
        __nv_bfloat16* XwH = (t & 1) ? Xh0 : Xh1;
        __nv_bfloat16* XwL = (t & 1) ? Xl0 : Xl1;

        {
            GArgs b{};
            b.Ah = XrH; b.Al = XrL; b.lda = XK;
            b.Bh = sym<__nv_bfloat16>(g_WcatT_h); b.Bl = sym<__nv_bfloat16>(g_WcatT_l); b.ldb = XK;
            b.Ci = pBaseg; b.ldci = Gd; b.K = XK;
            b.cst = sym<float>(g_c);
            b.Xh = XwH; b.Xl = XwL;
            b.Ch = Ch; b.Cl = Cl;
            gemm<128,128,64,32,256,1,2><<<dim3(16, 32), 256, SM128128>>>(b);
        }
        {
            TailArgs ta{};
            ta.XwH = XwH; ta.XwL = XwL; ta.XwHm = XwH; ta.XwLm = XwL;
            ta.XrH = XrH; ta.XrL = XrL;
            ta.Ch = Ch; ta.Cl = Cl;
            ta.basehz = pBasehz;
            ta.b1 = b1; ta.b2 = b2; ta.b3 = b3;
            ta.W5 = W5; ta.b5 = b5; ta.W6 = W6; ta.b6 = b6;
            ta.W8 = W8; ta.b8 = b8; ta.W9 = W9; ta.b9 = b9;
            ta.eps_inf = eps_inf; ta.eps_pri = eps_pri;
            ta.fake = out_fake; ta.out_mean = out_mean; ta.out_lv = out_lv; ta.out_z = out_z;
            ta.t = t;
            tail_kernel<<<Bn / 32, 256, SMTAIL>>>(ta);
        }
    }
}

// round 8
// speedup vs baseline: 1.1187x; 1.0195x over previous
#include <cuda_runtime.h>
#include <cuda_bf16.h>
#include <math.h>
#include <stdint.h>

#define Bn   4096
#define Hd   512
#define Fd   256
#define Zd   64
#define Td   16
#define Gd   2048
#define XK   832      // bf16 X row: [z(64) | y(256) | h(512)]
#define IK   1024     // head K:     [c(512) | y_j(256) | y_prev(256)]
#define CK   512      // c buffer row

// ---------------- persistent buffers ----------------
__device__ float g_baseg [(size_t)Bn * Gd];
__device__ float g_basehz[Bn * 128];
__device__ float g_c     [Bn * Hd];
__device__ float g_blstmp[Gd];
__device__ float g_bhz   [128];

__device__ __nv_bfloat16 g_Xh0[(size_t)Bn * XK], g_Xl0[(size_t)Bn * XK];
__device__ __nv_bfloat16 g_Xh1[(size_t)Bn * XK], g_Xl1[(size_t)Bn * XK];
__device__ __nv_bfloat16 g_Ch [(size_t)Bn * CK], g_Cl [(size_t)Bn * CK];
__device__ __nv_bfloat16 g_hih[(size_t)Bn * Hd], g_hil[(size_t)Bn * Hd];

__device__ __nv_bfloat16 g_WcatT_h[(size_t)Gd * XK], g_WcatT_l[(size_t)Gd * XK];
__device__ __nv_bfloat16 g_WxhT_h [(size_t)Gd * Hd], g_WxhT_l [(size_t)Gd * Hd];
__device__ __nv_bfloat16 g_W1T_h  [Fd * Hd], g_W1T_l  [Fd * Hd];
__device__ __nv_bfloat16 g_W2T_h  [Fd * Fd], g_W2T_l  [Fd * Fd];
__device__ __nv_bfloat16 g_W3T_h  [Fd * Fd], g_W3T_l  [Fd * Fd];
__device__ __nv_bfloat16 g_WheadT_h[128 * IK], g_WheadT_l[128 * IK];
__device__ __nv_bfloat16 g_WbaseT_h[128 * Hd], g_WbaseT_l[128 * Hd];

// ---------------- helpers ----------------
__device__ __forceinline__ void bsplit(float v, __nv_bfloat16& h, __nv_bfloat16& l) {
    h = __float2bfloat16_rn(v);
    l = __float2bfloat16_rn(v - __bfloat162float(h));
}
__device__ __forceinline__ uint32_t bpack(__nv_bfloat16 a, __nv_bfloat16 b) {
    __nv_bfloat162 t; t.x = a; t.y = b;
    return reinterpret_cast<uint32_t&>(t);
}
__device__ __forceinline__ __nv_bfloat162 bmk2(__nv_bfloat16 a, __nv_bfloat16 b) {
    __nv_bfloat162 t; t.x = a; t.y = b; return t;
}
__device__ __forceinline__ void mma16816(float* c, const uint32_t* a, const uint32_t* b) {
    asm volatile(
        "mma.sync.aligned.m16n8k16.row.col.f32.bf16.bf16.f32 "
        "{%0,%1,%2,%3}, {%4,%5,%6,%7}, {%8,%9}, {%0,%1,%2,%3};\n"
        : "+f"(c[0]), "+f"(c[1]), "+f"(c[2]), "+f"(c[3])
        : "r"(a[0]), "r"(a[1]), "r"(a[2]), "r"(a[3]), "r"(b[0]), "r"(b[1]));
}
__device__ __forceinline__ void ldsm4(uint32_t& r0, uint32_t& r1, uint32_t& r2, uint32_t& r3,
                                      uint32_t addr) {
    asm volatile("ldmatrix.sync.aligned.m8n8.x4.shared.b16 {%0,%1,%2,%3}, [%4];"
        : "=r"(r0), "=r"(r1), "=r"(r2), "=r"(r3) : "r"(addr));
}
__device__ __forceinline__ void cpa16(void* dst, const void* src) {
    uint32_t d = (uint32_t)__cvta_generic_to_shared(dst);
    asm volatile("cp.async.cg.shared.global [%0], [%1], 16;\n" :: "r"(d), "l"(src));
}
#define CPA_COMMIT() asm volatile("cp.async.commit_group;\n")
#define CPA_WAIT1()  asm volatile("cp.async.wait_group 1;\n")
#define CPA_WAIT0()  asm volatile("cp.async.wait_group 0;\n")

// ldmatrix-based stage mma. Layout: rows of 80B (16 k-pair words + 16B pad),
// hi at base, lo at base+HS. laneoff = (lane&15)*80 + (lane>>4)*16.
template<int MT,int NTL,int AHS,int BHS>
__device__ __forceinline__ void stage_mma2(const char* Ab, const char* Bb, float* acc,
                                           int wm, int wn, int laneoff)
{
    uint32_t aH = (uint32_t)__cvta_generic_to_shared(Ab) + laneoff;
    uint32_t bH = (uint32_t)__cvta_generic_to_shared(Bb) + laneoff;
#pragma unroll
    for (int kk = 0; kk < 2; kk++) {
        const int kb = kk * 32;
        uint32_t bhf[NTL][2], blf[NTL][2];
#pragma unroll
        for (int np = 0; np < NTL / 2; np++) {
            uint32_t r0, r1, r2, r3;
            ldsm4(r0, r1, r2, r3, bH + (wn + np * 16) * 80 + kb);
            bhf[2*np][0] = r0; bhf[2*np+1][0] = r1; bhf[2*np][1] = r2; bhf[2*np+1][1] = r3;
            ldsm4(r0, r1, r2, r3, bH + BHS + (wn + np * 16) * 80 + kb);
            blf[2*np][0] = r0; blf[2*np+1][0] = r1; blf[2*np][1] = r2; blf[2*np+1][1] = r3;
        }
#pragma unroll
        for (int mt = 0; mt < MT; mt++) {
            uint32_t ah[4], al[4];
            ldsm4(ah[0], ah[1], ah[2], ah[3], aH + (wm + mt * 16) * 80 + kb);
            ldsm4(al[0], al[1], al[2], al[3], aH + AHS + (wm + mt * 16) * 80 + kb);
#pragma unroll
            for (int nt = 0; nt < NTL; nt++) {
                float* a = acc + (mt * NTL + nt) * 4;
                mma16816(a, ah, bhf[nt]);
                mma16816(a, ah, blf[nt]);
                mma16816(a, al, bhf[nt]);
            }
        }
    }
}

// ================= gate GEMM (+fused LSTM) =================
struct GArgs {
    const __nv_bfloat16 *Ah, *Al; int lda;
    const __nv_bfloat16 *Bh, *Bl; int ldb;
    const float* Ci; int ldci;
    float* C; int ldc;
    int K;
    float* cst;
    __nv_bfloat16 *Xh, *Xl;
    __nv_bfloat16 *Ch, *Cl;
};

template<int BM,int BN,int NTH>
__device__ __forceinline__ void stage_load(char* base, int tid, int bm, int bn,
    const __nv_bfloat16* Ah, const __nv_bfloat16* Al, int lda,
    const __nv_bfloat16* Bh, const __nv_bfloat16* Bl, int ldb, int k0)
{
#pragma unroll
    for (int i = tid; i < BM * 4; i += NTH) {
        int row = i >> 2, c4 = (i & 3) * 16;
        size_t off = ((size_t)(bm + row) * lda + k0) * 2 + c4;
        cpa16(base + row * 80 + c4, (const char*)Ah + off);
        cpa16(base + BM * 80 + row * 80 + c4, (const char*)Al + off);
    }
#pragma unroll
    for (int i = tid; i < BN * 4; i += NTH) {
        int row = i >> 2, c4 = (i & 3) * 16;
        size_t off = ((size_t)(bn + row) * ldb + k0) * 2 + c4;
        cpa16(base + BM * 160 + row * 80 + c4, (const char*)Bh + off);
        cpa16(base + BM * 160 + BN * 80 + row * 80 + c4, (const char*)Bl + off);
    }
    CPA_COMMIT();
}

template<int BM,int BN,int WM,int WN,int NTH,int EPI,int CI>
__global__ void __launch_bounds__(NTH) gemm(GArgs g)
{
    extern __shared__ char sm[];
    constexpr int MT = WM / 16, NTL = WN / 8, NWN = BN / WN;
    constexpr int stageB = (BM + BN) * 160;
    const int tid = threadIdx.x, warp = tid >> 5, lane = tid & 31;
    const int gq = lane >> 2, tg = lane & 3;
    const int laneoff = (lane & 15) * 80 + (lane >> 4) * 16;
    const int wm = (warp / NWN) * WM, wn = (warp % NWN) * WN;
    const int bm = blockIdx.y * BM, bn = blockIdx.x * BN;
    const int K = g.K;

    float acc[MT * NTL * 4];
#pragma unroll
    for (int i = 0; i < MT * NTL * 4; i++) acc[i] = 0.f;

    const int nk = K >> 5;
    stage_load<BM,BN,NTH>(sm, tid, bm, bn, g.Ah, g.Al, g.lda, g.Bh, g.Bl, g.ldb, 0);
    for (int kt = 0; kt < nk; kt++) {
        if (kt + 1 < nk) {
            stage_load<BM,BN,NTH>(sm + ((kt + 1) & 1) * stageB, tid, bm, bn,
                                  g.Ah, g.Al, g.lda, g.Bh, g.Bl, g.ldb, (kt + 1) << 5);
            CPA_WAIT1();
        } else {
            CPA_WAIT0();
        }
        __syncthreads();
        const char* cur = sm + (kt & 1) * stageB;
        stage_mma2<MT,NTL,BM*80,BN*80>(cur, cur + BM * 160, acc, wm, wn, laneoff);
        __syncthreads();
    }

    if (EPI == 1) {
        float* tile = (float*)sm;
#pragma unroll
        for (int mt = 0; mt < MT; mt++)
#pragma unroll
            for (int nt = 0; nt < NTL; nt++) {
                int r0 = wm + mt * 16 + gq, c0 = wn + nt * 8 + 2 * tg;
                float* a = acc + (mt * NTL + nt) * 4;
                const float* ci0 = g.Ci + (size_t)(bm + r0) * g.ldci + bn + c0;
                const float* ci1 = g.Ci + (size_t)(bm + r0 + 8) * g.ldci + bn + c0;
                tile[r0 * BN + c0]           = a[0] + ci0[0];
                tile[r0 * BN + c0 + 1]       = a[1] + ci0[1];
                tile[(r0 + 8) * BN + c0]     = a[2] + ci1[0];
                tile[(r0 + 8) * BN + c0 + 1] = a[3] + ci1[1];
            }
        __syncthreads();
        for (int idx = tid; idx < BM * 32; idx += NTH) {
            int row = idx >> 5, w = idx & 31;
            float ig = tile[row * BN + w];
            float fg = tile[row * BN + 32 + w];
            float gg = tile[row * BN + 64 + w];
            float og = tile[row * BN + 96 + w];
            int b = bm + row, j = blockIdx.x * 32 + w;
            float si = 1.f / (1.f + expf(-ig));
            float sf = 1.f / (1.f + expf(-fg));
            float so = 1.f / (1.f + expf(-og));
            float cn = sf * g.cst[b * Hd + j] + si * tanhf(gg);
            float hn = so * tanhf(cn);
            g.cst[b * Hd + j] = cn;
            __nv_bfloat16 hh, hl, ch, cl;
            bsplit(hn, hh, hl); bsplit(cn, ch, cl);
            g.Xh[(size_t)b * XK + 320 + j] = hh;
            g.Xl[(size_t)b * XK + 320 + j] = hl;
            g.Ch[(size_t)b * CK + j] = ch;
            g.Cl[(size_t)b * CK + j] = cl;
        }
        return;
    }

#pragma unroll
    for (int mt = 0; mt < MT; mt++)
#pragma unroll
        for (int nt = 0; nt < NTL; nt++) {
            float* a = acc + (mt * NTL + nt) * 4;
#pragma unroll
            for (int half = 0; half < 2; half++) {
                int r = bm + wm + mt * 16 + gq + half * 8;
                int c = bn + wn + nt * 8 + 2 * tg;
                float v0 = a[half * 2], v1 = a[half * 2 + 1];
                if (CI == 1) { v0 += g.Ci[c]; v1 += g.Ci[c + 1]; }
                *(float2*)&g.C[(size_t)r * g.ldc + c] = make_float2(v0, v1);
            }
        }
}

// ================= fused tail kernel (256 threads / 8 warps) =================
struct TailArgs {
    const __nv_bfloat16 *XwH, *XwL;
    __nv_bfloat16 *XwHm, *XwLm;
    const __nv_bfloat16 *XrH, *XrL;
    const __nv_bfloat16 *Ch, *Cl;
    const float* basehz;
    const float *b1, *b2, *b3;
    const float *W5, *b5, *W6, *b6, *W8, *b8, *W9, *b9;
    const float *eps_inf, *eps_pri;
    float *fake, *out_mean, *out_lv, *out_z;
    int t;
};

template<int BN,int NTH>
__device__ __forceinline__ void tail_loadB(char* st, int tid,
    const __nv_bfloat16* Bh, const __nv_bfloat16* Bl, int ldb, int kg)
{
#pragma unroll
    for (int i = tid; i < BN * 4; i += NTH) {
        int row = i >> 2, c4 = (i & 3) * 16;
        size_t off = ((size_t)row * ldb + kg) * 2 + c4;
        cpa16(st + row * 80 + c4, (const char*)Bh + off);
        cpa16(st + BN * 80 + row * 80 + c4, (const char*)Bl + off);
    }
}

__device__ __forceinline__ void tail_loadA(char* st, int tid, int r0,
    const __nv_bfloat16* Ah, const __nv_bfloat16* Al, int lda, int kg)
{
    if (tid >= 128) return;
    int arow = tid >> 2, ac4 = (tid & 3) * 16;
    size_t off = ((size_t)(r0 + arow) * lda + kg) * 2 + ac4;
    cpa16(st + arow * 80 + ac4, (const char*)Ah + off);
    cpa16(st + 2560 + arow * 80 + ac4, (const char*)Al + off);
}

template<int NTL>
__device__ __forceinline__ void epi_chunk(const float* acc, const float* bias,
                                          char* dst, int wn, int gq, int tg)
{
#pragma unroll
    for (int mt = 0; mt < 2; mt++)
#pragma unroll
        for (int nt = 0; nt < NTL; nt++)
#pragma unroll
            for (int half = 0; half < 2; half++) {
                int row = mt * 16 + gq + half * 8;
                int col = wn + nt * 8 + 2 * tg;
                const float* a = acc + (mt * NTL + nt) * 4 + half * 2;
                float v0 = fmaxf(a[0] + bias[col], 0.f);
                float v1 = fmaxf(a[1] + bias[col + 1], 0.f);
                __nv_bfloat16 h0, l0, h1, l1;
                bsplit(v0, h0, l0); bsplit(v1, h1, l1);
                char* cb = dst + (col >> 5) * 5120;
                int kp = (col & 31) >> 1;
                ((uint32_t*)cb)[row * 20 + kp] = bpack(h0, h1);
                ((uint32_t*)(cb + 2560))[row * 20 + kp] = bpack(l0, l1);
            }
}

__global__ void __launch_bounds__(256) tail_kernel(TailArgs g)
{
    extern __shared__ char sm[];
    char* stages = sm;
    char* tA = sm + 92160;
    char* tB = sm + 133120;
    float* hzc = (float*)tB;

    const int tid = threadIdx.x, lane = tid & 31, warp = tid >> 5;
    const int gq = lane >> 2, tg = lane & 3;
    const int laneoff = (lane & 15) * 80 + (lane >> 4) * 16;
    const int r0 = blockIdx.x * 32;
    constexpr int DST = 46080;
    constexpr int HST = 25600;

    // ---------- dec1: t1 = relu(h @ W1 + b1)  K=512, BN=256 ----------
    {
        float acc[32];
#pragma unroll
        for (int i = 0; i < 32; i++) acc[i] = 0.f;
        tail_loadA(stages, tid, r0, g.XwH + 320, g.XwL + 320, XK, 0);
        tail_loadB<256,256>(stages + 5120, tid, g_W1T_h, g_W1T_l, Hd, 0);
        CPA_COMMIT();
        for (int kt = 0; kt < 16; kt++) {
            char* cur = stages + (kt & 1) * DST;
            if (kt < 15) {
                char* nxt = stages + ((kt + 1) & 1) * DST;
                tail_loadA(nxt, tid, r0, g.XwH + 320, g.XwL + 320, XK, (kt + 1) * 32);
                tail_loadB<256,256>(nxt + 5120, tid, g_W1T_h, g_W1T_l, Hd, (kt + 1) * 32);
                CPA_COMMIT(); CPA_WAIT1();
            } else CPA_WAIT0();
            __syncthreads();
            stage_mma2<2,4,2560,20480>(cur, cur + 5120, acc, 0, warp * 32, laneoff);
            __syncthreads();
        }
        epi_chunk<4>(acc, g.b1, tA, warp * 32, gq, tg);
        __syncthreads();
    }
    // ---------- dec2 ----------
    {
        float acc[32];
#pragma unroll
        for (int i = 0; i < 32; i++) acc[i] = 0.f;
        tail_loadB<256,256>(stages + 5120, tid, g_W2T_h, g_W2T_l, Fd, 0);
        CPA_COMMIT();
        for (int kt = 0; kt < 8; kt++) {
            char* cur = stages + (kt & 1) * DST;
            if (kt < 7) {
                tail_loadB<256,256>(stages + ((kt + 1) & 1) * DST + 5120, tid,
                                    g_W2T_h, g_W2T_l, Fd, (kt + 1) * 32);
                CPA_COMMIT(); CPA_WAIT1();
            } else CPA_WAIT0();
            __syncthreads();
            stage_mma2<2,4,2560,20480>(tA + kt * 5120, cur + 5120, acc, 0, warp * 32, laneoff);
            __syncthreads();
        }
        epi_chunk<4>(acc, g.b2, tB, warp * 32, gq, tg);
        __syncthreads();
    }
    // ---------- dec3 ----------
    {
        float acc[32];
#pragma unroll
        for (int i = 0; i < 32; i++) acc[i] = 0.f;
        tail_loadB<256,256>(stages + 5120, tid, g_W3T_h, g_W3T_l, Fd, 0);
        CPA_COMMIT();
        for (int kt = 0; kt < 8; kt++) {
            char* cur = stages + (kt & 1) * DST;
            if (kt < 7) {
                tail_loadB<256,256>(stages + ((kt + 1) & 1) * DST + 5120, tid,
                                    g_W3T_h, g_W3T_l, Fd, (kt + 1) * 32);
                CPA_COMMIT(); CPA_WAIT1();
            } else CPA_WAIT0();
            __syncthreads();
            stage_mma2<2,4,2560,20480>(tB + kt * 5120, cur + 5120, acc, 0, warp * 32, laneoff);
            __syncthreads();
        }
#pragma unroll
        for (int mt = 0; mt < 2; mt++)
#pragma unroll
            for (int nt = 0; nt < 4; nt++)
#pragma unroll
                for (int half = 0; half < 2; half++) {
                    int row = mt * 16 + gq + half * 8;
                    int col = warp * 32 + nt * 8 + 2 * tg;
                    int b = r0 + row;
                    const float* a = acc + (mt * 4 + nt) * 4 + half * 2;
                    float v0 = fmaxf(a[0] + g.b3[col], 0.f);
                    float v1 = fmaxf(a[1] + g.b3[col + 1], 0.f);
                    *(float2*)&g.fake[(size_t)b * (Td * Fd) + g.t * Fd + col] = make_float2(v0, v1);
                    __nv_bfloat16 h0, l0, h1, l1;
                    bsplit(v0, h0, l0); bsplit(v1, h1, l1);
                    *(__nv_bfloat162*)&g.XwHm[(size_t)b * XK + 64 + col] = bmk2(h0, h1);
                    *(__nv_bfloat162*)&g.XwLm[(size_t)b * XK + 64 + col] = bmk2(l0, l1);
                    char* cb = tA + (col >> 5) * 5120;
                    int kp = (col & 31) >> 1;
                    ((uint32_t*)cb)[row * 20 + kp] = bpack(h0, h1);
                    ((uint32_t*)(cb + 2560))[row * 20 + kp] = bpack(l0, l1);
                }
        __syncthreads();
    }
    // ---------- head ----------
    {
        float acc[16];
#pragma unroll
        for (int i = 0; i < 16; i++) acc[i] = 0.f;
        tail_loadA(stages, tid, r0, g.Ch, g.Cl, CK, 0);
        tail_loadB<128,256>(stages + 5120, tid, g_WheadT_h, g_WheadT_l, IK, 0);
        CPA_COMMIT();
        for (int kt = 0; kt < 32; kt++) {
            char* cur = stages + (kt & 1) * HST;
            if (kt < 31) {
                char* nxt = stages + ((kt + 1) & 1) * HST;
                int kn = kt + 1;
                if (kn < 16)       tail_loadA(nxt, tid, r0, g.Ch, g.Cl, CK, kn * 32);
                else if (kn >= 24) tail_loadA(nxt, tid, r0, g.XrH, g.XrL, XK, 64 + (kn - 24) * 32);
                tail_loadB<128,256>(nxt + 5120, tid, g_WheadT_h, g_WheadT_l, IK, kn * 32);
                CPA_COMMIT(); CPA_WAIT1();
            } else CPA_WAIT0();
            __syncthreads();
            const char* Ab = (kt >= 16 && kt < 24) ? (tA + (kt - 16) * 5120) : cur;
            stage_mma2<2,2,2560,10240>(Ab, cur + 5120, acc, 0, warp * 16, laneoff);
            __syncthreads();
        }
#pragma unroll
        for (int mt = 0; mt < 2; mt++)
#pragma unroll
            for (int nt = 0; nt < 2; nt++)
#pragma unroll
                for (int half = 0; half < 2; half++) {
                    int row = mt * 16 + gq + half * 8;
                    int col = warp * 16 + nt * 8 + 2 * tg;
                    const float* a = acc + (mt * 2 + nt) * 4 + half * 2;
                    const float* bz = g.basehz + (size_t)(r0 + row) * 128 + col;
                    hzc[row * 130 + col]     = fmaxf(a[0] + bz[0], 0.f);
                    hzc[row * 130 + col + 1] = fmaxf(a[1] + bz[1], 0.f);
                }
        __syncthreads();
    }
    // ---------- finish ----------
    for (int idx = tid; idx < 32 * 64; idx += 256) {
        int row = idx >> 6, z = idx & 63, b = r0 + row;
        float m = g.b5[z], l = g.b6[z], mp = g.b8[z], lp = g.b9[z];
        const float* hz = &hzc[row * 130];
#pragma unroll 8
        for (int k = 0; k < 64; k++) {
            float av = hz[k], ap = hz[64 + k];
            m  += av * g.W5[k * Zd + z];
            l  += av * g.W6[k * Zd + z];
            mp += ap * g.W8[k * Zd + z];
            lp += ap * g.W9[k * Zd + z];
        }
        m = fmaxf(m, 0.f); l = fmaxf(l, 0.f); mp = fmaxf(mp, 0.f); lp = fmaxf(lp, 0.f);
        size_t gi = (size_t)b * Zd + z;
        float zi = m  + g.eps_inf[(size_t)g.t * Bn * Zd + gi] * sqrtf(expf(l));
        float zp = mp + g.eps_pri[(size_t)g.t * Bn * Zd + gi] * sqrtf(expf(lp));
        g.out_mean[(size_t)b * Td * Zd + (size_t)g.t * Zd + z] = m;
        g.out_lv  [(size_t)b * Td * Zd + (size_t)g.t * Zd + z] = l;
        g.out_z[(size_t)(2 * g.t)     * Bn * Zd + gi] = zi;
        g.out_z[(size_t)(2 * g.t + 1) * Bn * Zd + gi] = zp;
        __nv_bfloat16 zh, zl; bsplit(zi, zh, zl);
        g.XwHm[(size_t)b * XK + z] = zh;
        g.XwLm[(size_t)b * XK + z] = zl;
    }
}

// ---------------- single merged prep kernel ----------------
__device__ __forceinline__ int perm_n(int np) {
    int chunk = np >> 7, r = np & 127, gate = r >> 5, w = r & 31;
    return gate * 512 + chunk * 32 + w;
}

__global__ void prep_all(const float* __restrict__ h_i,
                         const float* __restrict__ Wx, const float* __restrict__ Wh,
                         const float* __restrict__ bl,
                         const float* __restrict__ W1, const float* __restrict__ W2,
                         const float* __restrict__ W3,
                         const float* __restrict__ W4, const float* __restrict__ W7,
                         const float* __restrict__ b4, const float* __restrict__ b7)
{
    size_t i = (size_t)blockIdx.x * blockDim.x + threadIdx.x;
    __nv_bfloat16 h, l;

    const size_t nX = (size_t)Bn * XK;
    if (i < nX) {
        __nv_bfloat16 z = __float2bfloat16(0.f);
        g_Xh0[i] = z; g_Xl0[i] = z; g_Xh1[i] = z; g_Xl1[i] = z;
        return;
    }
    i -= nX;
    const size_t nC = (size_t)Bn * Hd;
    if (i < nC) { g_c[i] = 0.f; return; }
    i -= nC;
    if (i < (size_t)Bn * Hd) {
        bsplit(h_i[i], h, l);
        g_hih[i] = h; g_hil[i] = l;
        return;
    }
    i -= (size_t)Bn * Hd;
    if (i < (size_t)Gd * XK) {
        int k = (int)(i % XK), np = (int)(i / XK);
        int n = perm_n(np);
        float v;
        if (k < 64)       v = Wx[(size_t)k * Gd + n];
        else if (k < 320) v = Wx[(size_t)(512 + k) * Gd + n];
        else              v = Wh[(size_t)(k - 320) * Gd + n];
        bsplit(v, h, l);
        g_WcatT_h[i] = h; g_WcatT_l[i] = l;
        return;
    }
    i -= (size_t)Gd * XK;
    if (i < (size_t)Gd * Hd) {
        int k = (int)(i % Hd), np = (int)(i / Hd);
        int n = perm_n(np);
        bsplit(Wx[(size_t)(64 + k) * Gd + n], h, l);
        g_WxhT_h[i] = h; g_WxhT_l[i] = l;
        if (k == 0) g_blstmp[np] = bl[n];
        return;
    }
    i -= (size_t)Gd * Hd;
    if (i < (size_t)Fd * Hd) {
        int k = (int)(i % Hd), n = (int)(i / Hd);
        bsplit(W1[(size_t)k * Fd + n], h, l);
        g_W1T_h[i] = h; g_W1T_l[i] = l;
        return;
    }
    i -= (size_t)Fd * Hd;
    if (i < (size_t)Fd * Fd) {
        int k = (int)(i % Fd), n = (int)(i / Fd);
        bsplit(W2[(size_t)k * Fd + n], h, l);
        g_W2T_h[i] = h; g_W2T_l[i] = l;
        return;
    }
    i -= (size_t)Fd * Fd;
    if (i < (size_t)Fd * Fd) {
        int k = (int)(i % Fd), n = (int)(i / Fd);
        bsplit(W3[(size_t)k * Fd + n], h, l);
        g_W3T_h[i] = h; g_W3T_l[i] = l;
        return;
    }
    i -= (size_t)Fd * Fd;
    if (i < (size_t)128 * IK) {
        int k = (int)(i % IK), n = (int)(i / IK);
        float v;
        if (n < 64) v = W4[(size_t)(512 + k) * Zd + n];
        else {
            int n2 = n - 64;
            if (k < 512)      v = W7[(size_t)(512 + k) * Zd + n2];
            else if (k < 768) v = 0.f;
            else              v = W7[(size_t)(1024 + k - 768) * Zd + n2];
        }
        bsplit(v, h, l);
        g_WheadT_h[i] = h; g_WheadT_l[i] = l;
        return;
    }
    i -= (size_t)128 * IK;
    if (i < (size_t)128 * Hd) {
        int k = (int)(i % Hd), n = (int)(i / Hd);
        float v = (n < 64) ? W4[(size_t)k * Zd + n] : W7[(size_t)k * Zd + (n - 64)];
        bsplit(v, h, l);
        g_WbaseT_h[i] = h; g_WbaseT_l[i] = l;
        if (k == 0) g_bhz[n] = (n < 64) ? b4[n] : b7[n - 64];
    }
}

// ---------------- host ----------------
template<typename T> static T* sym(const void* s) { void* p = nullptr; cudaGetSymbolAddress(&p, s); return (T*)p; }

extern "C" void kernel_launch(void* const* d_in, const int* in_sizes, int n_in,
                              void* d_out, int out_size) {
    const float* h_i     = (const float*)d_in[0];
    const float* eps_inf = (const float*)d_in[1];
    const float* eps_pri = (const float*)d_in[2];
    const float* Wx      = (const float*)d_in[3];
    const float* Wh      = (const float*)d_in[4];
    const float* b_lstm  = (const float*)d_in[5];
    const float* W1 = (const float*)d_in[6],  *b1 = (const float*)d_in[7];
    const float* W2 = (const float*)d_in[8],  *b2 = (const float*)d_in[9];
    const float* W3 = (const float*)d_in[10], *b3 = (const float*)d_in[11];
    const float* W4 = (const float*)d_in[12], *b4 = (const float*)d_in[13];
    const float* W5 = (const float*)d_in[14], *b5 = (const float*)d_in[15];
    const float* W6 = (const float*)d_in[16], *b6 = (const float*)d_in[17];
    const float* W7 = (const float*)d_in[18], *b7 = (const float*)d_in[19];
    const float* W8 = (const float*)d_in[20], *b8 = (const float*)d_in[21];
    const float* W9 = (const float*)d_in[22], *b9 = (const float*)d_in[23];

    float* out      = (float*)d_out;
    float* out_fake = out;
    float* out_mean = out_fake + (size_t)Bn * Td * Fd;
    float* out_lv   = out_mean + (size_t)Bn * Td * Zd;
    float* out_z    = out_lv   + (size_t)Bn * Td * Zd;

    __nv_bfloat16* Xh0 = sym<__nv_bfloat16>(g_Xh0); __nv_bfloat16* Xl0 = sym<__nv_bfloat16>(g_Xl0);
    __nv_bfloat16* Xh1 = sym<__nv_bfloat16>(g_Xh1); __nv_bfloat16* Xl1 = sym<__nv_bfloat16>(g_Xl1);
    __nv_bfloat16* Ch  = sym<__nv_bfloat16>(g_Ch);  __nv_bfloat16* Cl  = sym<__nv_bfloat16>(g_Cl);

    float* pBaseg  = sym<float>(g_baseg);
    float* pBasehz = sym<float>(g_basehz);
    float* pBlstmp = sym<float>(g_blstmp);
    float* pBhz    = sym<float>(g_bhz);

    constexpr int SM128128 = (128 + 128) * 160 * 2;   // 81920
    constexpr int SM6464   = (64 + 64) * 160 * 2;     // 40960
    constexpr int SMTAIL   = 174080;
    cudaFuncSetAttribute(gemm<128,128,64,64,128,0,1>, cudaFuncAttributeMaxDynamicSharedMemorySize, SM128128);
    cudaFuncSetAttribute(gemm<128,128,64,64,128,1,2>, cudaFuncAttributeMaxDynamicSharedMemorySize, SM128128);
    cudaFuncSetAttribute(gemm<64,64,32,32,128,0,1>,   cudaFuncAttributeMaxDynamicSharedMemorySize, SM6464);
    cudaFuncSetAttribute(tail_kernel,                 cudaFuncAttributeMaxDynamicSharedMemorySize, SMTAIL);

    // ---- init (single launch) ----
    {
        size_t tot = (size_t)Bn * XK + 2 * (size_t)Bn * Hd
                   + (size_t)Gd * XK + (size_t)Gd * Hd
                   + (size_t)Fd * Hd + 2 * (size_t)Fd * Fd
                   + (size_t)128 * IK + (size_t)128 * Hd;
        prep_all<<<(unsigned)((tot + 255) / 256), 256>>>(h_i, Wx, Wh, b_lstm,
                                                         W1, W2, W3, W4, W7, b4, b7);
    }

    // ---- hoisted base GEMMs ----
    {
        GArgs b{};
        b.Ah = sym<__nv_bfloat16>(g_hih); b.Al = sym<__nv_bfloat16>(g_hil); b.lda = Hd;
        b.Bh = sym<__nv_bfloat16>(g_WxhT_h); b.Bl = sym<__nv_bfloat16>(g_WxhT_l); b.ldb = Hd;
        b.Ci = pBlstmp; b.C = pBaseg; b.ldc = Gd; b.K = Hd;
        gemm<128,128,64,64,128,0,1><<<dim3(16, 32), 128, SM128128>>>(b);

        b.Bh = sym<__nv_bfloat16>(g_WbaseT_h); b.Bl = sym<__nv_bfloat16>(g_WbaseT_l); b.ldb = Hd;
        b.Ci = pBhz; b.C = pBasehz; b.ldc = 128; b.K = Hd;
        gemm<64,64,32,32,128,0,1><<<dim3(2, 64), 128, SM6464>>>(b);
    }

    for (int t = 0; t < Td; t++) {
        __nv_bfloat16* XrH = (t & 1) ? Xh1 : Xh0;
        __nv_bfloat16* XrL = (t & 1) ? Xl1 : Xl0;
        __nv_bfloat16* XwH = (t & 1) ? Xh0 : Xh1;
        __nv_bfloat16* XwL = (t & 1) ? Xl0 : Xl1;

        {
            GArgs b{};
            b.Ah = XrH; b.Al = XrL; b.lda = XK;
            b.Bh = sym<__nv_bfloat16>(g_WcatT_h); b.Bl = sym<__nv_bfloat16>(g_WcatT_l); b.ldb = XK;
            b.Ci = pBaseg; b.ldci = Gd; b.K = XK;
            b.cst = sym<float>(g_c);
            b.Xh = XwH; b.Xl = XwL;
            b.Ch = Ch; b.Cl = Cl;
            gemm<128,128,64,64,128,1,2><<<dim3(16, 32), 128, SM128128>>>(b);
        }
        {
            TailArgs ta{};
            ta.XwH = XwH; ta.XwL = XwL; ta.XwHm = XwH; ta.XwLm = XwL;
            ta.XrH = XrH; ta.XrL = XrL;
            ta.Ch = Ch; ta.Cl = Cl;
            ta.basehz = pBasehz;
            ta.b1 = b1; ta.b2 = b2; ta.b3 = b3;
            ta.W5 = W5; ta.b5 = b5; ta.W6 = W6; ta.b6 = b6;
            ta.W8 = W8; ta.b8 = b8; ta.W9 = W9; ta.b9 = b9;
            ta.eps_inf = eps_inf; ta.eps_pri = eps_pri;
            ta.fake = out_fake; ta.out_mean = out_mean; ta.out_lv = out_lv; ta.out_z = out_z;
            ta.t = t;
            tail_kernel<<<Bn / 32, 256, SMTAIL>>>(ta);
        }
    }
}